// round 2
// baseline (speedup 1.0000x reference)
#include <cuda_runtime.h>
#include <cstddef>

// ---------------------------------------------------------------------------
// Problem constants
// ---------------------------------------------------------------------------
#define BB  2
#define LL  2048
#define DD  512
#define HH  8
#define DHH 64
#define DFC 2048
#define MM  (BB * LL)        // 4096 rows

// Scratch (device globals: allocation-guard-safe)
__device__ float g_Q[MM * DD];
__device__ float g_K[MM * DD];
__device__ float g_V[MM * DD];
__device__ float g_A[MM * DD];        // attention output (B,L,D)
__device__ float g_Hbuf[MM * DFC];    // FFN hidden

// ---------------------------------------------------------------------------
// SGEMM: C[M,N] = A[M,K] @ B[K,N] + bias[N]  (optional ReLU)
// 128x128 block tile, BK=16, 256 threads, 8x8 per-thread microtile.
// All shapes here divide evenly; no bounds checks.
// ---------------------------------------------------------------------------
template <bool RELU>
__device__ __forceinline__ void sgemm_body(const float* __restrict__ A,
                                           const float* __restrict__ B,
                                           const float* __restrict__ bias,
                                           float* __restrict__ C,
                                           int M, int N, int K)
{
    __shared__ float As[16][132];   // [k][m], transposed A tile
    __shared__ float Bs[16][132];   // [k][n]

    const int tid = threadIdx.x;
    const int tx = tid & 15;        // 0..15 -> 8 cols each
    const int ty = tid >> 4;        // 0..15 -> 8 rows each
    const int m0 = blockIdx.y * 128;
    const int n0 = blockIdx.x * 128;

    float acc[8][8];
#pragma unroll
    for (int r = 0; r < 8; r++)
#pragma unroll
        for (int c = 0; c < 8; c++) acc[r][c] = 0.0f;

    const int ar  = tid >> 2;       // 0..63 (row within tile, +64 for second)
    const int akq = tid & 3;        // float4 slot along k

    for (int k0 = 0; k0 < K; k0 += 16) {
        // Load A tile (128x16) transposed into As[k][m]
#pragma unroll
        for (int i = 0; i < 2; i++) {
            int row = ar + 64 * i;
            float4 v = *(const float4*)&A[(size_t)(m0 + row) * K + k0 + 4 * akq];
            As[4 * akq + 0][row] = v.x;
            As[4 * akq + 1][row] = v.y;
            As[4 * akq + 2][row] = v.z;
            As[4 * akq + 3][row] = v.w;
        }
        // Load B tile (16x128) natural into Bs[k][n]
#pragma unroll
        for (int i = 0; i < 2; i++) {
            int idx = tid + 256 * i;      // 0..511 float4 slots
            int kr  = idx >> 5;           // 0..15
            int nq  = idx & 31;           // 0..31
            float4 v = *(const float4*)&B[(size_t)(k0 + kr) * N + n0 + 4 * nq];
            *(float4*)&Bs[kr][4 * nq] = v;
        }
        __syncthreads();

#pragma unroll
        for (int kk = 0; kk < 16; kk++) {
            float a[8], b[8];
            *(float4*)&a[0] = *(const float4*)&As[kk][8 * ty];
            *(float4*)&a[4] = *(const float4*)&As[kk][8 * ty + 4];
            *(float4*)&b[0] = *(const float4*)&Bs[kk][8 * tx];
            *(float4*)&b[4] = *(const float4*)&Bs[kk][8 * tx + 4];
#pragma unroll
            for (int r = 0; r < 8; r++)
#pragma unroll
                for (int c = 0; c < 8; c++)
                    acc[r][c] = fmaf(a[r], b[c], acc[r][c]);
        }
        __syncthreads();
    }

    // Epilogue
    float bb[8];
#pragma unroll
    for (int c = 0; c < 8; c++) bb[c] = bias[n0 + 8 * tx + c];

#pragma unroll
    for (int r = 0; r < 8; r++) {
        int m = m0 + 8 * ty + r;
        float4 v0, v1;
        float out[8];
#pragma unroll
        for (int c = 0; c < 8; c++) {
            float v = acc[r][c] + bb[c];
            if (RELU) v = fmaxf(v, 0.0f);
            out[c] = v;
        }
        v0 = *(float4*)&out[0];
        v1 = *(float4*)&out[4];
        *(float4*)&C[(size_t)m * N + n0 + 8 * tx]     = v0;
        *(float4*)&C[(size_t)m * N + n0 + 8 * tx + 4] = v1;
    }
}

__global__ __launch_bounds__(256, 2)
void sgemm_kernel(const float* __restrict__ A, const float* __restrict__ B,
                  const float* __restrict__ bias, float* __restrict__ C,
                  int M, int N, int K)
{
    sgemm_body<false>(A, B, bias, C, M, N, K);
}

__global__ __launch_bounds__(256, 2)
void sgemm_relu_kernel(const float* __restrict__ A, const float* __restrict__ B,
                       const float* __restrict__ bias, float* __restrict__ C,
                       int M, int N, int K)
{
    sgemm_body<true>(A, B, bias, C, M, N, K);
}

// Fused QKV: grid.z selects which projection; all three run in one launch.
__global__ __launch_bounds__(256, 2)
void qkv_kernel(const float* __restrict__ x,
                const float* __restrict__ wq, const float* __restrict__ bq,
                const float* __restrict__ wk, const float* __restrict__ bk,
                const float* __restrict__ wv, const float* __restrict__ bv,
                float* __restrict__ Q, float* __restrict__ K, float* __restrict__ V)
{
    const float* B; const float* bias; float* C;
    if (blockIdx.z == 0)      { B = wq; bias = bq; C = Q; }
    else if (blockIdx.z == 1) { B = wk; bias = bk; C = K; }
    else                      { B = wv; bias = bv; C = V; }
    sgemm_body<false>(x, B, bias, C, MM, DD, DD);
}

// ---------------------------------------------------------------------------
// Flash attention with relative position bias (music-transformer skew).
//   logits[i,j] = (Q_i.K_j + Q_i.rel_emb[2047-(i-j)]) / 8   for j <= i
// Tiles: 64 queries x 64 keys, DH=64. 256 threads (16x16), 4x4 microtiles.
// Relative bias: per key tile t (j0 = i0-64t), distances d = 64t+di-dj span
// chunks t-1 and t of F[d] = rel_emb[2047-d]. We compute R_t = Qtile @ F_t^T
// (one extra 64x64x64 GEMM per tile) and ping-pong chunks through smem,
// gathering diagonals.
// ---------------------------------------------------------------------------
#define ATS 68   // smem row stride (64 + 4 pad)

__global__ __launch_bounds__(256, 2)
void attn_kernel(const float* __restrict__ Q, const float* __restrict__ K,
                 const float* __restrict__ V, const float* __restrict__ rel,
                 float* __restrict__ Out)
{
    extern __shared__ float sm[];
    float* Qs  = sm;                 // [k][di]
    float* Ks  = sm + 1 * 64 * ATS;  // [k][dj]
    float* Vs  = sm + 2 * 64 * ATS;  // [dj][k]
    float* FPs = sm + 3 * 64 * ATS;  // F chunk [k][dc], later P [di][dj]
    float* Rs0 = sm + 4 * 64 * ATS;  // R chunk ping [di][col]
    float* Rs1 = sm + 5 * 64 * ATS;  // R chunk pong

    const int qi = blockIdx.x;
    const int h  = blockIdx.y;
    const int b  = blockIdx.z;
    const int i0 = qi * 64;
    const int tid = threadIdx.x;
    const int tx = tid & 15;
    const int ty = tid >> 4;
    const float scale = 0.125f;      // 1/sqrt(64)

    const int lr  = tid >> 2;        // load row 0..63
    const int lq4 = tid & 3;         // load float4 phase

    // Load Q tile transposed: Qs[k][di]
    {
        const float* src = Q + ((size_t)(b * LL + i0 + lr) * DD + h * DHH);
#pragma unroll
        for (int it = 0; it < 4; it++) {
            int f = lq4 + 4 * it;
            float4 v = *(const float4*)(src + 4 * f);
            Qs[(4 * f + 0) * ATS + lr] = v.x;
            Qs[(4 * f + 1) * ATS + lr] = v.y;
            Qs[(4 * f + 2) * ATS + lr] = v.z;
            Qs[(4 * f + 3) * ATS + lr] = v.w;
        }
    }

    float O[4][4];
    float mrow[4], lrow[4];
#pragma unroll
    for (int r = 0; r < 4; r++) {
        mrow[r] = -1e30f; lrow[r] = 0.0f;
#pragma unroll
        for (int c = 0; c < 4; c++) O[r][c] = 0.0f;
    }

    int cur = 0;
    for (int t = 0; t <= qi; t++) {
        const int j0 = i0 - 64 * t;
        __syncthreads();   // previous iteration's smem consumers done (also covers Q load at t=0)

        // Load K (transposed), F chunk t (transposed), V (natural)
        {
            const float* ksrc = K + ((size_t)(b * LL + j0 + lr) * DD + h * DHH);
            const float* vsrc = V + ((size_t)(b * LL + j0 + lr) * DD + h * DHH);
            const int d = 64 * t + lr;                       // distance for F row
            const float* fsrc = rel + ((size_t)(LL - 1 - d) * DD + h * DHH);
#pragma unroll
            for (int it = 0; it < 4; it++) {
                int f = lq4 + 4 * it;
                float4 kv = *(const float4*)(ksrc + 4 * f);
                Ks[(4 * f + 0) * ATS + lr] = kv.x;
                Ks[(4 * f + 1) * ATS + lr] = kv.y;
                Ks[(4 * f + 2) * ATS + lr] = kv.z;
                Ks[(4 * f + 3) * ATS + lr] = kv.w;
                float4 fv = *(const float4*)(fsrc + 4 * f);
                FPs[(4 * f + 0) * ATS + lr] = fv.x;
                FPs[(4 * f + 1) * ATS + lr] = fv.y;
                FPs[(4 * f + 2) * ATS + lr] = fv.z;
                FPs[(4 * f + 3) * ATS + lr] = fv.w;
                float4 vv = *(const float4*)(vsrc + 4 * f);
                *(float4*)&Vs[lr * ATS + 4 * f] = vv;
            }
        }
        __syncthreads();

        // S = Qtile @ Ktile^T,  Rnew = Qtile @ Fchunk^T
        float s[4][4], rn[4][4];
#pragma unroll
        for (int r = 0; r < 4; r++)
#pragma unroll
            for (int c = 0; c < 4; c++) { s[r][c] = 0.0f; rn[r][c] = 0.0f; }

#pragma unroll 8
        for (int kk = 0; kk < 64; kk++) {
            float4 qv = *(const float4*)&Qs[kk * ATS + 4 * ty];
            float4 kv = *(const float4*)&Ks[kk * ATS + 4 * tx];
            float4 fv = *(const float4*)&FPs[kk * ATS + 4 * tx];
            float qa[4] = {qv.x, qv.y, qv.z, qv.w};
            float kb[4] = {kv.x, kv.y, kv.z, kv.w};
            float fb[4] = {fv.x, fv.y, fv.z, fv.w};
#pragma unroll
            for (int r = 0; r < 4; r++)
#pragma unroll
                for (int c = 0; c < 4; c++) {
                    s[r][c]  = fmaf(qa[r], kb[c], s[r][c]);
                    rn[r][c] = fmaf(qa[r], fb[c], rn[r][c]);
                }
        }

        // Publish Rnew chunk
        float* Rc = cur ? Rs1 : Rs0;
        float* Rp = cur ? Rs0 : Rs1;
#pragma unroll
        for (int r = 0; r < 4; r++)
#pragma unroll
            for (int c = 0; c < 4; c++)
                Rc[(4 * ty + r) * ATS + 4 * tx + c] = rn[r][c];
        __syncthreads();

        // Gather diagonals, mask, scale; online softmax update
        float mx[4];
#pragma unroll
        for (int r = 0; r < 4; r++) {
            const int di = 4 * ty + r;
            float rowm = -1e30f;
#pragma unroll
            for (int c = 0; c < 4; c++) {
                const int dj = 4 * tx + c;
                const int diff = di - dj;                  // d = 64t + diff
                float relv = (diff >= 0) ? Rc[di * ATS + diff]
                                         : Rp[di * ATS + 64 + diff];
                float sv = (s[r][c] + relv) * scale;
                if (t == 0 && diff < 0) sv = -1e30f;       // causal mask (diag tile)
                s[r][c] = sv;
                rowm = fmaxf(rowm, sv);
            }
            rowm = fmaxf(rowm, __shfl_xor_sync(0xffffffffu, rowm, 8));
            rowm = fmaxf(rowm, __shfl_xor_sync(0xffffffffu, rowm, 4));
            rowm = fmaxf(rowm, __shfl_xor_sync(0xffffffffu, rowm, 2));
            rowm = fmaxf(rowm, __shfl_xor_sync(0xffffffffu, rowm, 1));
            mx[r] = rowm;
        }

        // exp + write P into FPs (FPs free: all threads passed the sync above)
#pragma unroll
        for (int r = 0; r < 4; r++) {
            const int di = 4 * ty + r;
            const float mnew = fmaxf(mrow[r], mx[r]);
            const float alpha = __expf(mrow[r] - mnew);
            mrow[r] = mnew;
            float rsum = 0.0f;
#pragma unroll
            for (int c = 0; c < 4; c++) {
                float e = __expf(s[r][c] - mnew);
                rsum += e;
                FPs[di * ATS + 4 * tx + c] = e;
            }
            rsum += __shfl_xor_sync(0xffffffffu, rsum, 8);
            rsum += __shfl_xor_sync(0xffffffffu, rsum, 4);
            rsum += __shfl_xor_sync(0xffffffffu, rsum, 2);
            rsum += __shfl_xor_sync(0xffffffffu, rsum, 1);
            lrow[r] = lrow[r] * alpha + rsum;
#pragma unroll
            for (int c = 0; c < 4; c++) O[r][c] *= alpha;
        }
        __syncthreads();

        // O += P @ Vtile
#pragma unroll 8
        for (int dj = 0; dj < 64; dj++) {
            float4 vv = *(const float4*)&Vs[dj * ATS + 4 * tx];
            float vb[4] = {vv.x, vv.y, vv.z, vv.w};
#pragma unroll
            for (int r = 0; r < 4; r++) {
                float pv = FPs[(4 * ty + r) * ATS + dj];
#pragma unroll
                for (int c = 0; c < 4; c++)
                    O[r][c] = fmaf(pv, vb[c], O[r][c]);
            }
        }
        cur ^= 1;
    }

    // Normalize and write: Out[b, i0+di, h, dc]  (forms (B,L,D) row-major)
#pragma unroll
    for (int r = 0; r < 4; r++) {
        const int di = 4 * ty + r;
        const float inv = 1.0f / lrow[r];
        float out[4];
#pragma unroll
        for (int c = 0; c < 4; c++) out[c] = O[r][c] * inv;
        float* dst = Out + ((size_t)(b * LL + i0 + di) * DD + h * DHH + 4 * tx);
        *(float4*)dst = *(float4*)&out[0];
    }
}

// ---------------------------------------------------------------------------
// Launch
// ---------------------------------------------------------------------------
extern "C" void kernel_launch(void* const* d_in, const int* in_sizes, int n_in,
                              void* d_out, int out_size)
{
    const float* x   = (const float*)d_in[0];
    // d_in[1] = mask (additive causal) — implemented analytically in attn_kernel
    const float* wq  = (const float*)d_in[2];
    const float* bq  = (const float*)d_in[3];
    const float* wk  = (const float*)d_in[4];
    const float* bk  = (const float*)d_in[5];
    const float* wv  = (const float*)d_in[6];
    const float* bv  = (const float*)d_in[7];
    const float* rel = (const float*)d_in[8];
    const float* w1  = (const float*)d_in[9];
    const float* b1  = (const float*)d_in[10];
    const float* w2  = (const float*)d_in[11];
    const float* b2  = (const float*)d_in[12];
    float* out = (float*)d_out;

    float *Qp, *Kp, *Vp, *Ap, *Hp;
    cudaGetSymbolAddress((void**)&Qp, g_Q);
    cudaGetSymbolAddress((void**)&Kp, g_K);
    cudaGetSymbolAddress((void**)&Vp, g_V);
    cudaGetSymbolAddress((void**)&Ap, g_A);
    cudaGetSymbolAddress((void**)&Hp, g_Hbuf);

    // 1) QKV projections (fused grid, z selects matrix)
    qkv_kernel<<<dim3(DD / 128, MM / 128, 3), 256>>>(x, wq, bq, wk, bk, wv, bv,
                                                     Qp, Kp, Vp);

    // 2) Flash attention with relative bias
    const size_t attn_smem = 6 * 64 * ATS * sizeof(float);  // ~104 KB
    cudaFuncSetAttribute(attn_kernel, cudaFuncAttributeMaxDynamicSharedMemorySize,
                         (int)attn_smem);
    attn_kernel<<<dim3(LL / 64, HH, BB), 256, attn_smem>>>(Qp, Kp, Vp, rel, Ap);

    // 3) FFN
    sgemm_relu_kernel<<<dim3(DFC / 128, MM / 128), 256>>>(Ap, w1, b1, Hp,
                                                          MM, DFC, DD);
    sgemm_kernel<<<dim3(DD / 128, MM / 128), 256>>>(Hp, w2, b2, out,
                                                    MM, DD, DFC);
}

// round 3
// speedup vs baseline: 1.0496x; 1.0496x over previous
#include <cuda_runtime.h>
#include <cstddef>

// ---------------------------------------------------------------------------
// Problem constants
// ---------------------------------------------------------------------------
#define BB  2
#define LL  2048
#define DD  512
#define HH  8
#define DHH 64
#define DFC 2048
#define MM  (BB * LL)        // 4096 rows

typedef unsigned long long u64;

// Scratch (device globals: allocation-guard-safe)
__device__ float g_Q[MM * DD];
__device__ float g_K[MM * DD];
__device__ float g_V[MM * DD];
__device__ float g_A[MM * DD];        // attention output (B,L,D)
__device__ float g_Hbuf[MM * DFC];    // FFN hidden

// ---------------------------------------------------------------------------
// Packed fp32x2 helpers (SASS FFMA2 path — only reachable via PTX f32x2)
// Bit-identical to two scalar IEEE fp32 FMAs.
// ---------------------------------------------------------------------------
__device__ __forceinline__ u64 dup2(float x) {
    u64 r; asm("mov.b64 %0, {%1, %1};" : "=l"(r) : "f"(x)); return r;
}
__device__ __forceinline__ void fma2(u64& d, u64 a, u64 b) {
    asm("fma.rn.f32x2 %0, %1, %2, %0;" : "+l"(d) : "l"(a), "l"(b));
}
__device__ __forceinline__ u64 mul2(u64 a, u64 b) {
    u64 r; asm("mul.rn.f32x2 %0, %1, %2;" : "=l"(r) : "l"(a), "l"(b)); return r;
}
__device__ __forceinline__ float2 unpk2(u64 v) {
    float2 f; asm("mov.b64 {%0, %1}, %2;" : "=f"(f.x), "=f"(f.y) : "l"(v)); return f;
}

// ---------------------------------------------------------------------------
// SGEMM: C[M,N] = A[M,K] @ B[K,N] + bias[N]  (optional ReLU)
// 128x128 block tile, BK=16, 256 threads, 8x8 per-thread microtile via FFMA2.
// ---------------------------------------------------------------------------
template <bool RELU>
__device__ __forceinline__ void sgemm_body(const float* __restrict__ A,
                                           const float* __restrict__ B,
                                           const float* __restrict__ bias,
                                           float* __restrict__ C,
                                           int M, int N, int K)
{
    __shared__ __align__(16) float As[16][132];   // [k][m], transposed A tile
    __shared__ __align__(16) float Bs[16][132];   // [k][n]  (132*4 = 528 B, 16-aligned rows)

    const int tid = threadIdx.x;
    const int tx = tid & 15;        // 0..15 -> 8 cols each
    const int ty = tid >> 4;        // 0..15 -> 8 rows each
    const int m0 = blockIdx.y * 128;
    const int n0 = blockIdx.x * 128;

    u64 acc2[8][4];                 // 8 rows x 4 col-pairs
#pragma unroll
    for (int r = 0; r < 8; r++)
#pragma unroll
        for (int c = 0; c < 4; c++) acc2[r][c] = 0ull;

    const int ar  = tid >> 2;       // 0..63 (row within tile, +64 for second)
    const int akq = tid & 3;        // float4 slot along k

    for (int k0 = 0; k0 < K; k0 += 16) {
        // Load A tile (128x16) transposed into As[k][m]
#pragma unroll
        for (int i = 0; i < 2; i++) {
            int row = ar + 64 * i;
            float4 v = *(const float4*)&A[(size_t)(m0 + row) * K + k0 + 4 * akq];
            As[4 * akq + 0][row] = v.x;
            As[4 * akq + 1][row] = v.y;
            As[4 * akq + 2][row] = v.z;
            As[4 * akq + 3][row] = v.w;
        }
        // Load B tile (16x128) natural into Bs[k][n]
#pragma unroll
        for (int i = 0; i < 2; i++) {
            int idx = tid + 256 * i;      // 0..511 float4 slots
            int kr  = idx >> 5;           // 0..15
            int nq  = idx & 31;           // 0..31
            float4 v = *(const float4*)&B[(size_t)(k0 + kr) * N + n0 + 4 * nq];
            *(float4*)&Bs[kr][4 * nq] = v;
        }
        __syncthreads();

#pragma unroll
        for (int kk = 0; kk < 16; kk++) {
            float a[8];
            *(float4*)&a[0] = *(const float4*)&As[kk][8 * ty];
            *(float4*)&a[4] = *(const float4*)&As[kk][8 * ty + 4];
            ulonglong2 b01 = *(const ulonglong2*)&Bs[kk][8 * tx];
            ulonglong2 b23 = *(const ulonglong2*)&Bs[kk][8 * tx + 4];
            u64 bp[4] = {b01.x, b01.y, b23.x, b23.y};
#pragma unroll
            for (int r = 0; r < 8; r++) {
                u64 ad = dup2(a[r]);
#pragma unroll
                for (int c = 0; c < 4; c++)
                    fma2(acc2[r][c], ad, bp[c]);
            }
        }
        __syncthreads();
    }

    // Epilogue
    float bb[8];
#pragma unroll
    for (int c = 0; c < 8; c++) bb[c] = bias[n0 + 8 * tx + c];

#pragma unroll
    for (int r = 0; r < 8; r++) {
        int m = m0 + 8 * ty + r;
        float out[8];
#pragma unroll
        for (int c = 0; c < 4; c++) {
            float2 v = unpk2(acc2[r][c]);
            float v0 = v.x + bb[2 * c];
            float v1 = v.y + bb[2 * c + 1];
            if (RELU) { v0 = fmaxf(v0, 0.0f); v1 = fmaxf(v1, 0.0f); }
            out[2 * c] = v0; out[2 * c + 1] = v1;
        }
        *(float4*)&C[(size_t)m * N + n0 + 8 * tx]     = *(float4*)&out[0];
        *(float4*)&C[(size_t)m * N + n0 + 8 * tx + 4] = *(float4*)&out[4];
    }
}

__global__ __launch_bounds__(256, 2)
void sgemm_kernel(const float* __restrict__ A, const float* __restrict__ B,
                  const float* __restrict__ bias, float* __restrict__ C,
                  int M, int N, int K)
{
    sgemm_body<false>(A, B, bias, C, M, N, K);
}

__global__ __launch_bounds__(256, 2)
void sgemm_relu_kernel(const float* __restrict__ A, const float* __restrict__ B,
                       const float* __restrict__ bias, float* __restrict__ C,
                       int M, int N, int K)
{
    sgemm_body<true>(A, B, bias, C, M, N, K);
}

// Fused QKV: grid.z selects which projection; all three run in one launch.
__global__ __launch_bounds__(256, 2)
void qkv_kernel(const float* __restrict__ x,
                const float* __restrict__ wq, const float* __restrict__ bq,
                const float* __restrict__ wk, const float* __restrict__ bk,
                const float* __restrict__ wv, const float* __restrict__ bv,
                float* __restrict__ Q, float* __restrict__ K, float* __restrict__ V)
{
    const float* B; const float* bias; float* C;
    if (blockIdx.z == 0)      { B = wq; bias = bq; C = Q; }
    else if (blockIdx.z == 1) { B = wk; bias = bk; C = K; }
    else                      { B = wv; bias = bv; C = V; }
    sgemm_body<false>(x, B, bias, C, MM, DD, DD);
}

// ---------------------------------------------------------------------------
// Flash attention with relative position bias (music-transformer skew).
//   logits[i,j] = (Q_i.K_j + Q_i.rel_emb[2047-(i-j)]) / 8   for j <= i
// Tiles: 64 queries x 64 keys, DH=64. 256 threads (16x16), 4x4 microtiles.
// Inner GEMMs (S, R, PV) run on the packed FFMA2 path.
// ---------------------------------------------------------------------------
#define ATS 68   // smem row stride (64 + 4 pad); 68*4 = 272 B, 16-aligned

__global__ __launch_bounds__(256, 2)
void attn_kernel(const float* __restrict__ Q, const float* __restrict__ K,
                 const float* __restrict__ V, const float* __restrict__ rel,
                 float* __restrict__ Out)
{
    extern __shared__ float sm[];
    float* Qs  = sm;                 // [k][di]
    float* Ks  = sm + 1 * 64 * ATS;  // [k][dj]
    float* Vs  = sm + 2 * 64 * ATS;  // [dj][k]
    float* FPs = sm + 3 * 64 * ATS;  // F chunk [k][dc], later P [di][dj]
    float* Rs0 = sm + 4 * 64 * ATS;  // R chunk ping [di][col]
    float* Rs1 = sm + 5 * 64 * ATS;  // R chunk pong

    const int qi = blockIdx.x;
    const int h  = blockIdx.y;
    const int b  = blockIdx.z;
    const int i0 = qi * 64;
    const int tid = threadIdx.x;
    const int tx = tid & 15;
    const int ty = tid >> 4;
    const float scale = 0.125f;      // 1/sqrt(64)

    const int lr  = tid >> 2;        // load row 0..63
    const int lq4 = tid & 3;         // load float4 phase

    // Load Q tile transposed: Qs[k][di]
    {
        const float* src = Q + ((size_t)(b * LL + i0 + lr) * DD + h * DHH);
#pragma unroll
        for (int it = 0; it < 4; it++) {
            int f = lq4 + 4 * it;
            float4 v = *(const float4*)(src + 4 * f);
            Qs[(4 * f + 0) * ATS + lr] = v.x;
            Qs[(4 * f + 1) * ATS + lr] = v.y;
            Qs[(4 * f + 2) * ATS + lr] = v.z;
            Qs[(4 * f + 3) * ATS + lr] = v.w;
        }
    }

    u64 O2[4][2];                       // 4 rows x 2 col-pairs
    float mrow[4], lrow[4];
#pragma unroll
    for (int r = 0; r < 4; r++) {
        mrow[r] = -1e30f; lrow[r] = 0.0f;
        O2[r][0] = 0ull; O2[r][1] = 0ull;
    }

    int cur = 0;
    for (int t = 0; t <= qi; t++) {
        const int j0 = i0 - 64 * t;
        __syncthreads();   // previous iteration's smem consumers done

        // Load K (transposed), F chunk t (transposed), V (natural)
        {
            const float* ksrc = K + ((size_t)(b * LL + j0 + lr) * DD + h * DHH);
            const float* vsrc = V + ((size_t)(b * LL + j0 + lr) * DD + h * DHH);
            const int d = 64 * t + lr;                       // distance for F row
            const float* fsrc = rel + ((size_t)(LL - 1 - d) * DD + h * DHH);
#pragma unroll
            for (int it = 0; it < 4; it++) {
                int f = lq4 + 4 * it;
                float4 kv = *(const float4*)(ksrc + 4 * f);
                Ks[(4 * f + 0) * ATS + lr] = kv.x;
                Ks[(4 * f + 1) * ATS + lr] = kv.y;
                Ks[(4 * f + 2) * ATS + lr] = kv.z;
                Ks[(4 * f + 3) * ATS + lr] = kv.w;
                float4 fv = *(const float4*)(fsrc + 4 * f);
                FPs[(4 * f + 0) * ATS + lr] = fv.x;
                FPs[(4 * f + 1) * ATS + lr] = fv.y;
                FPs[(4 * f + 2) * ATS + lr] = fv.z;
                FPs[(4 * f + 3) * ATS + lr] = fv.w;
                float4 vv = *(const float4*)(vsrc + 4 * f);
                *(float4*)&Vs[lr * ATS + 4 * f] = vv;
            }
        }
        __syncthreads();

        // S = Qtile @ Ktile^T,  Rnew = Qtile @ Fchunk^T  (FFMA2 path)
        u64 s2[4][2], rn2[4][2];
#pragma unroll
        for (int r = 0; r < 4; r++) {
            s2[r][0] = s2[r][1] = 0ull;
            rn2[r][0] = rn2[r][1] = 0ull;
        }

#pragma unroll 8
        for (int kk = 0; kk < 64; kk++) {
            float4 qv = *(const float4*)&Qs[kk * ATS + 4 * ty];
            ulonglong2 kp = *(const ulonglong2*)&Ks[kk * ATS + 4 * tx];
            ulonglong2 fp = *(const ulonglong2*)&FPs[kk * ATS + 4 * tx];
            float qa[4] = {qv.x, qv.y, qv.z, qv.w};
#pragma unroll
            for (int r = 0; r < 4; r++) {
                u64 qd = dup2(qa[r]);
                fma2(s2[r][0], qd, kp.x);
                fma2(s2[r][1], qd, kp.y);
                fma2(rn2[r][0], qd, fp.x);
                fma2(rn2[r][1], qd, fp.y);
            }
        }

        // Unpack
        float s[4][4], rn[4][4];
#pragma unroll
        for (int r = 0; r < 4; r++) {
            float2 v0 = unpk2(s2[r][0]);  float2 v1 = unpk2(s2[r][1]);
            s[r][0] = v0.x; s[r][1] = v0.y; s[r][2] = v1.x; s[r][3] = v1.y;
            float2 w0 = unpk2(rn2[r][0]); float2 w1 = unpk2(rn2[r][1]);
            rn[r][0] = w0.x; rn[r][1] = w0.y; rn[r][2] = w1.x; rn[r][3] = w1.y;
        }

        // Publish Rnew chunk
        float* Rc = cur ? Rs1 : Rs0;
        float* Rp = cur ? Rs0 : Rs1;
#pragma unroll
        for (int r = 0; r < 4; r++)
#pragma unroll
            for (int c = 0; c < 4; c++)
                Rc[(4 * ty + r) * ATS + 4 * tx + c] = rn[r][c];
        __syncthreads();

        // Gather diagonals, mask, scale; online softmax update
        float mx[4];
#pragma unroll
        for (int r = 0; r < 4; r++) {
            const int di = 4 * ty + r;
            float rowm = -1e30f;
#pragma unroll
            for (int c = 0; c < 4; c++) {
                const int dj = 4 * tx + c;
                const int diff = di - dj;                  // d = 64t + diff
                float relv = (diff >= 0) ? Rc[di * ATS + diff]
                                         : Rp[di * ATS + 64 + diff];
                float sv = (s[r][c] + relv) * scale;
                if (t == 0 && diff < 0) sv = -1e30f;       // causal mask (diag tile)
                s[r][c] = sv;
                rowm = fmaxf(rowm, sv);
            }
            rowm = fmaxf(rowm, __shfl_xor_sync(0xffffffffu, rowm, 8));
            rowm = fmaxf(rowm, __shfl_xor_sync(0xffffffffu, rowm, 4));
            rowm = fmaxf(rowm, __shfl_xor_sync(0xffffffffu, rowm, 2));
            rowm = fmaxf(rowm, __shfl_xor_sync(0xffffffffu, rowm, 1));
            mx[r] = rowm;
        }

        // exp + write P into FPs (FPs free: all threads passed the sync above)
#pragma unroll
        for (int r = 0; r < 4; r++) {
            const int di = 4 * ty + r;
            const float mnew = fmaxf(mrow[r], mx[r]);
            const float alpha = __expf(mrow[r] - mnew);
            mrow[r] = mnew;
            float rsum = 0.0f;
#pragma unroll
            for (int c = 0; c < 4; c++) {
                float e = __expf(s[r][c] - mnew);
                rsum += e;
                FPs[di * ATS + 4 * tx + c] = e;
            }
            rsum += __shfl_xor_sync(0xffffffffu, rsum, 8);
            rsum += __shfl_xor_sync(0xffffffffu, rsum, 4);
            rsum += __shfl_xor_sync(0xffffffffu, rsum, 2);
            rsum += __shfl_xor_sync(0xffffffffu, rsum, 1);
            lrow[r] = lrow[r] * alpha + rsum;
            u64 ad = dup2(alpha);
            O2[r][0] = mul2(O2[r][0], ad);
            O2[r][1] = mul2(O2[r][1], ad);
        }
        __syncthreads();

        // O += P @ Vtile  (FFMA2 path)
#pragma unroll 8
        for (int dj = 0; dj < 64; dj++) {
            ulonglong2 vp = *(const ulonglong2*)&Vs[dj * ATS + 4 * tx];
#pragma unroll
            for (int r = 0; r < 4; r++) {
                u64 pd = dup2(FPs[(4 * ty + r) * ATS + dj]);
                fma2(O2[r][0], pd, vp.x);
                fma2(O2[r][1], pd, vp.y);
            }
        }
        cur ^= 1;
    }

    // Normalize and write: Out[b, i0+di, h, dc]  (forms (B,L,D) row-major)
#pragma unroll
    for (int r = 0; r < 4; r++) {
        const int di = 4 * ty + r;
        const float inv = 1.0f / lrow[r];
        float2 v0 = unpk2(O2[r][0]);
        float2 v1 = unpk2(O2[r][1]);
        float out[4] = {v0.x * inv, v0.y * inv, v1.x * inv, v1.y * inv};
        float* dst = Out + ((size_t)(b * LL + i0 + di) * DD + h * DHH + 4 * tx);
        *(float4*)dst = *(float4*)&out[0];
    }
}

// ---------------------------------------------------------------------------
// Launch
// ---------------------------------------------------------------------------
extern "C" void kernel_launch(void* const* d_in, const int* in_sizes, int n_in,
                              void* d_out, int out_size)
{
    const float* x   = (const float*)d_in[0];
    // d_in[1] = mask (additive causal) — implemented analytically in attn_kernel
    const float* wq  = (const float*)d_in[2];
    const float* bq  = (const float*)d_in[3];
    const float* wk  = (const float*)d_in[4];
    const float* bk  = (const float*)d_in[5];
    const float* wv  = (const float*)d_in[6];
    const float* bv  = (const float*)d_in[7];
    const float* rel = (const float*)d_in[8];
    const float* w1  = (const float*)d_in[9];
    const float* b1  = (const float*)d_in[10];
    const float* w2  = (const float*)d_in[11];
    const float* b2  = (const float*)d_in[12];
    float* out = (float*)d_out;

    float *Qp, *Kp, *Vp, *Ap, *Hp;
    cudaGetSymbolAddress((void**)&Qp, g_Q);
    cudaGetSymbolAddress((void**)&Kp, g_K);
    cudaGetSymbolAddress((void**)&Vp, g_V);
    cudaGetSymbolAddress((void**)&Ap, g_A);
    cudaGetSymbolAddress((void**)&Hp, g_Hbuf);

    // 1) QKV projections (fused grid, z selects matrix)
    qkv_kernel<<<dim3(DD / 128, MM / 128, 3), 256>>>(x, wq, bq, wk, bk, wv, bv,
                                                     Qp, Kp, Vp);

    // 2) Flash attention with relative bias
    const size_t attn_smem = 6 * 64 * ATS * sizeof(float);  // ~104 KB
    cudaFuncSetAttribute(attn_kernel, cudaFuncAttributeMaxDynamicSharedMemorySize,
                         (int)attn_smem);
    attn_kernel<<<dim3(LL / 64, HH, BB), 256, attn_smem>>>(Qp, Kp, Vp, rel, Ap);

    // 3) FFN
    sgemm_relu_kernel<<<dim3(DFC / 128, MM / 128), 256>>>(Ap, w1, b1, Hp,
                                                          MM, DFC, DD);
    sgemm_kernel<<<dim3(DD / 128, MM / 128), 256>>>(Hp, w2, b2, out,
                                                    MM, DD, DFC);
}

// round 6
// speedup vs baseline: 1.4614x; 1.3923x over previous
#include <cuda_runtime.h>
#include <cuda_bf16.h>
#include <cstdint>
#include <cstddef>

// ---------------------------------------------------------------------------
// Problem constants
// ---------------------------------------------------------------------------
#define BB   2
#define LL   2048
#define DD   512
#define HH   8
#define DHH  64
#define DFCN 2048
#define MM   (BB * LL)        // 4096 rows

typedef unsigned long long u64;
typedef unsigned int u32;

// ---------------------------------------------------------------------------
// Scratch (device globals: allocation-guard-safe)
// ---------------------------------------------------------------------------
__device__ float g_Q[MM * DD];
__device__ float g_K[MM * DD];
__device__ float g_V[MM * DD];
__device__ float g_A[MM * DD];                 // attention output (B,L,D) fp32

__device__ __nv_bfloat16 g_xh[MM * DD],   g_xl[MM * DD];      // split x
__device__ __nv_bfloat16 g_ah[MM * DD],   g_al[MM * DD];      // split attn out
__device__ __nv_bfloat16 g_hh[MM * DFCN], g_hl[MM * DFCN];    // split FFN hidden

// Transposed + split weights: T[n][k] = W[k][n]
__device__ __nv_bfloat16 g_wqh[DD * DD],   g_wql[DD * DD];
__device__ __nv_bfloat16 g_wkh[DD * DD],   g_wkl[DD * DD];
__device__ __nv_bfloat16 g_wvh[DD * DD],   g_wvl[DD * DD];
__device__ __nv_bfloat16 g_w1h[DFCN * DD], g_w1l[DFCN * DD];  // [2048][512]
__device__ __nv_bfloat16 g_w2h[DD * DFCN], g_w2l[DD * DFCN];  // [512][2048]

// ---------------------------------------------------------------------------
// Helpers
// ---------------------------------------------------------------------------
__device__ __forceinline__ u32 smem_u32(const void* p) {
    u32 a;
    asm("{ .reg .u64 t; cvta.to.shared.u64 t, %1; cvt.u32.u64 %0, t; }"
        : "=r"(a) : "l"(p));
    return a;
}

__device__ __forceinline__ u32 pack_bf2(__nv_bfloat16 a, __nv_bfloat16 b) {
    return (u32)__bfloat16_as_ushort(a) | ((u32)__bfloat16_as_ushort(b) << 16);
}

#define LDSM_X4(r, addr) \
    asm volatile("ldmatrix.sync.aligned.m8n8.x4.shared.b16 {%0,%1,%2,%3}, [%4];" \
        : "=r"((r)[0]), "=r"((r)[1]), "=r"((r)[2]), "=r"((r)[3]) : "r"(addr))

#define MMA_BF16(d, a, b0, b1) \
    asm volatile("mma.sync.aligned.m16n8k16.row.col.f32.bf16.bf16.f32 " \
        "{%0,%1,%2,%3}, {%4,%5,%6,%7}, {%8,%9}, {%0,%1,%2,%3};" \
        : "+f"((d)[0]), "+f"((d)[1]), "+f"((d)[2]), "+f"((d)[3]) \
        : "r"((a)[0]), "r"((a)[1]), "r"((a)[2]), "r"((a)[3]), "r"(b0), "r"(b1))

__device__ __forceinline__ void cp16(u32 dst, const void* src) {
    asm volatile("cp.async.cg.shared.global [%0], [%1], 16;"
                 :: "r"(dst), "l"(src) : "memory");
}
#define CP_COMMIT()  asm volatile("cp.async.commit_group;" ::: "memory")
#define CP_WAIT(n)   asm volatile("cp.async.wait_group %0;" :: "n"(n) : "memory")

// ---------------------------------------------------------------------------
// Weight transpose + bf16 split: W[K][N] fp32 -> Th/Tl[N][K] bf16
// ---------------------------------------------------------------------------
__global__ __launch_bounds__(256)
void transpose_split_kernel(const float* __restrict__ W,
                            __nv_bfloat16* __restrict__ Th,
                            __nv_bfloat16* __restrict__ Tl,
                            int K, int N)
{
    __shared__ float t[32][33];
    const int n0 = blockIdx.x * 32, k0 = blockIdx.y * 32;
    const int tx = threadIdx.x & 31, ty = threadIdx.x >> 5;   // ty 0..7
#pragma unroll
    for (int i = 0; i < 4; i++) {
        int k = k0 + ty + 8 * i;
        t[ty + 8 * i][tx] = W[(size_t)k * N + n0 + tx];
    }
    __syncthreads();
#pragma unroll
    for (int i = 0; i < 4; i++) {
        int n = n0 + ty + 8 * i;
        float v = t[tx][ty + 8 * i];
        __nv_bfloat16 h = __float2bfloat16(v);
        float r = v - __bfloat162float(h);
        Th[(size_t)n * K + k0 + tx] = h;
        Tl[(size_t)n * K + k0 + tx] = __float2bfloat16(r);
    }
}

// ---------------------------------------------------------------------------
// Elementwise bf16 split of an fp32 tensor (row-major preserved)
// ---------------------------------------------------------------------------
__global__ __launch_bounds__(256)
void convert_split_kernel(const float4* __restrict__ X,
                          __nv_bfloat16* __restrict__ H,
                          __nv_bfloat16* __restrict__ L, int n4)
{
    int i = blockIdx.x * blockDim.x + threadIdx.x;
    if (i >= n4) return;
    float4 v = X[i];
    __nv_bfloat16 h0 = __float2bfloat16(v.x), h1 = __float2bfloat16(v.y);
    __nv_bfloat16 h2 = __float2bfloat16(v.z), h3 = __float2bfloat16(v.w);
    uint2 hp, lp;
    hp.x = pack_bf2(h0, h1); hp.y = pack_bf2(h2, h3);
    lp.x = pack_bf2(__float2bfloat16(v.x - __bfloat162float(h0)),
                    __float2bfloat16(v.y - __bfloat162float(h1)));
    lp.y = pack_bf2(__float2bfloat16(v.z - __bfloat162float(h2)),
                    __float2bfloat16(v.w - __bfloat162float(h3)));
    *(uint2*)(H + 4 * (size_t)i) = hp;
    *(uint2*)(L + 4 * (size_t)i) = lp;
}

// ---------------------------------------------------------------------------
// Tensor-core split-bf16 GEMM via mma.sync (HMMA, works on plain sm_103):
//   C = A @ B^T + bias, A as (Ah,Al) [M][K], B as (Bh,Bl) [N][K], all bf16.
//   fp32 register accumulation: D = Ah·Bh + Ah·Bl + Al·Bh.
// 128x128x32 CTA tile, 8 warps (2x4), 64x32 warp tile, cp.async double buffer.
// Smem: 64B rows (32 bf16), 16B chunk swizzle c ^= (row>>1)&3 (ldmatrix
// conflict-free). MODE 0: Cf = D + bias fp32. MODE 1: relu split -> (Ch, Cl).
// ---------------------------------------------------------------------------
#define TG_TILE_BYTES  8192            // 128 x 32 x 2B
#define TG_STAGE_BYTES 32768           // Ah, Al, Bh, Bl
#define TG_SMEM        (2 * TG_STAGE_BYTES)

__device__ __forceinline__ void load_tile_cp(const __nv_bfloat16* __restrict__ src,
                                             int ldk, u32 sdst, int tid)
{
    // 128 rows x 4 16B chunks = 512 chunk loads, 256 threads x 2
#pragma unroll
    for (int i = 0; i < 2; i++) {
        int idx = tid + 256 * i;
        int r = idx >> 2, c = idx & 3;
        u32 dst = sdst + r * 64 + 16 * (c ^ ((r >> 1) & 3));
        cp16(dst, src + (size_t)r * ldk + 8 * c);
    }
}

template <int MODE>
__global__ __launch_bounds__(256, 1)
void tgemm_kernel(const __nv_bfloat16* __restrict__ Ah,
                  const __nv_bfloat16* __restrict__ Al,
                  const __nv_bfloat16* __restrict__ Bh,
                  const __nv_bfloat16* __restrict__ Bl,
                  const float* __restrict__ bias,
                  float* __restrict__ Cf,
                  __nv_bfloat16* __restrict__ Ch,
                  __nv_bfloat16* __restrict__ Cl,
                  int M, int N, int K)
{
    extern __shared__ char smem[];
    const u32 sb = smem_u32(smem);
    const int tid  = threadIdx.x;
    const int wid  = tid >> 5, lane = tid & 31;
    const int wm   = wid >> 2, wn = wid & 3;        // 2 x 4 warp grid
    const int m0   = blockIdx.y * 128;
    const int n0   = blockIdx.x * 128;
    const int NC   = K >> 5;                        // chunks of BK=32

    float acc[4][4][4];
#pragma unroll
    for (int mt = 0; mt < 4; mt++)
#pragma unroll
        for (int nt = 0; nt < 4; nt++)
#pragma unroll
            for (int r = 0; r < 4; r++) acc[mt][nt][r] = 0.0f;

    const __nv_bfloat16* Abase_h = Ah + (size_t)m0 * K;
    const __nv_bfloat16* Abase_l = Al + (size_t)m0 * K;
    const __nv_bfloat16* Bbase_h = Bh + (size_t)n0 * K;
    const __nv_bfloat16* Bbase_l = Bl + (size_t)n0 * K;

    // prologue: stage 0
    {
        u32 base = sb;
        load_tile_cp(Abase_h, K, base,                     tid);
        load_tile_cp(Abase_l, K, base + TG_TILE_BYTES,     tid);
        load_tile_cp(Bbase_h, K, base + 2 * TG_TILE_BYTES, tid);
        load_tile_cp(Bbase_l, K, base + 3 * TG_TILE_BYTES, tid);
        CP_COMMIT();
    }

    // Precompute ldmatrix lane row/chunk components
    const int lrow  = lane & 15;          // row within 16-row group
    const int lcol  = lane >> 4;          // chunk phase 0/1

    for (int c = 0; c < NC; c++) {
        if (c + 1 < NC) {
            u32 base = sb + ((c + 1) & 1) * TG_STAGE_BYTES;
            const int kofs = (c + 1) * 32;
            load_tile_cp(Abase_h + kofs, K, base,                     tid);
            load_tile_cp(Abase_l + kofs, K, base + TG_TILE_BYTES,     tid);
            load_tile_cp(Bbase_h + kofs, K, base + 2 * TG_TILE_BYTES, tid);
            load_tile_cp(Bbase_l + kofs, K, base + 3 * TG_TILE_BYTES, tid);
            CP_COMMIT();
            CP_WAIT(1);
        } else {
            CP_WAIT(0);
        }
        __syncthreads();

        const u32 base = sb + (c & 1) * TG_STAGE_BYTES;
        const u32 sAh = base;
        const u32 sAl = base + TG_TILE_BYTES;
        const u32 sBh = base + 2 * TG_TILE_BYTES;
        const u32 sBl = base + 3 * TG_TILE_BYTES;

#pragma unroll
        for (int ks = 0; ks < 2; ks++) {
            u32 ah[4][4], al[4][4], bh[2][4], bl[2][4];
#pragma unroll
            for (int mt = 0; mt < 4; mt++) {
                int r  = wm * 64 + mt * 16 + lrow;
                int ch = 2 * ks + lcol;
                u32 off = r * 64 + 16 * (ch ^ ((r >> 1) & 3));
                LDSM_X4(ah[mt], sAh + off);
                LDSM_X4(al[mt], sAl + off);
            }
#pragma unroll
            for (int ng = 0; ng < 2; ng++) {
                int r  = wn * 32 + ng * 16 + lrow;
                int ch = 2 * ks + lcol;
                u32 off = r * 64 + 16 * (ch ^ ((r >> 1) & 3));
                LDSM_X4(bh[ng], sBh + off);
                LDSM_X4(bl[ng], sBl + off);
            }
#pragma unroll
            for (int mt = 0; mt < 4; mt++)
#pragma unroll
                for (int nt = 0; nt < 4; nt++) {
                    const int ng = nt >> 1, hi = nt & 1;
                    MMA_BF16(acc[mt][nt], ah[mt], bh[ng][hi], bh[ng][2 + hi]);
                    MMA_BF16(acc[mt][nt], ah[mt], bl[ng][hi], bl[ng][2 + hi]);
                    MMA_BF16(acc[mt][nt], al[mt], bh[ng][hi], bh[ng][2 + hi]);
                }
        }
        __syncthreads();
    }

    // Epilogue: D frag thread map — rows t/4 (+8), cols 2*(t%4) (+1)
    const int tg = lane >> 2;
    const int tc = (lane & 3) * 2;
#pragma unroll
    for (int mt = 0; mt < 4; mt++) {
#pragma unroll
        for (int half = 0; half < 2; half++) {
            const int m = m0 + wm * 64 + mt * 16 + tg + 8 * half;
#pragma unroll
            for (int nt = 0; nt < 4; nt++) {
                const int n = n0 + wn * 32 + nt * 8 + tc;
                float v0 = acc[mt][nt][2 * half]     + bias[n];
                float v1 = acc[mt][nt][2 * half + 1] + bias[n + 1];
                if (MODE == 0) {
                    float2 o = make_float2(v0, v1);
                    *(float2*)(Cf + (size_t)m * N + n) = o;
                } else {
                    v0 = fmaxf(v0, 0.0f);
                    v1 = fmaxf(v1, 0.0f);
                    __nv_bfloat16 h0 = __float2bfloat16(v0);
                    __nv_bfloat16 h1 = __float2bfloat16(v1);
                    __nv_bfloat16 l0 = __float2bfloat16(v0 - __bfloat162float(h0));
                    __nv_bfloat16 l1 = __float2bfloat16(v1 - __bfloat162float(h1));
                    *(u32*)(Ch + (size_t)m * N + n) = pack_bf2(h0, h1);
                    *(u32*)(Cl + (size_t)m * N + n) = pack_bf2(l0, l1);
                }
            }
        }
    }
}

// ---------------------------------------------------------------------------
// Flash attention with relative position bias (round-3 version, FFMA2 path).
//   logits[i,j] = (Q_i.K_j + Q_i.rel_emb[2047-(i-j)]) / 8   for j <= i
// ---------------------------------------------------------------------------
__device__ __forceinline__ u64 dup2(float x) {
    u64 r; asm("mov.b64 %0, {%1, %1};" : "=l"(r) : "f"(x)); return r;
}
__device__ __forceinline__ void fma2(u64& d, u64 a, u64 b) {
    asm("fma.rn.f32x2 %0, %1, %2, %0;" : "+l"(d) : "l"(a), "l"(b));
}
__device__ __forceinline__ u64 mul2(u64 a, u64 b) {
    u64 r; asm("mul.rn.f32x2 %0, %1, %2;" : "=l"(r) : "l"(a), "l"(b)); return r;
}
__device__ __forceinline__ float2 unpk2(u64 v) {
    float2 f; asm("mov.b64 {%0, %1}, %2;" : "=f"(f.x), "=f"(f.y) : "l"(v)); return f;
}

#define ATS 68

__global__ __launch_bounds__(256, 2)
void attn_kernel(const float* __restrict__ Q, const float* __restrict__ K,
                 const float* __restrict__ V, const float* __restrict__ rel,
                 float* __restrict__ Out)
{
    extern __shared__ float sm[];
    float* Qs  = sm;
    float* Ks  = sm + 1 * 64 * ATS;
    float* Vs  = sm + 2 * 64 * ATS;
    float* FPs = sm + 3 * 64 * ATS;
    float* Rs0 = sm + 4 * 64 * ATS;
    float* Rs1 = sm + 5 * 64 * ATS;

    const int qi = blockIdx.x;
    const int h  = blockIdx.y;
    const int b  = blockIdx.z;
    const int i0 = qi * 64;
    const int tid = threadIdx.x;
    const int tx = tid & 15;
    const int ty = tid >> 4;
    const float scale = 0.125f;

    const int lr  = tid >> 2;
    const int lq4 = tid & 3;

    {
        const float* src = Q + ((size_t)(b * LL + i0 + lr) * DD + h * DHH);
#pragma unroll
        for (int it = 0; it < 4; it++) {
            int f = lq4 + 4 * it;
            float4 v = *(const float4*)(src + 4 * f);
            Qs[(4 * f + 0) * ATS + lr] = v.x;
            Qs[(4 * f + 1) * ATS + lr] = v.y;
            Qs[(4 * f + 2) * ATS + lr] = v.z;
            Qs[(4 * f + 3) * ATS + lr] = v.w;
        }
    }

    u64 O2[4][2];
    float mrow[4], lrow[4];
#pragma unroll
    for (int r = 0; r < 4; r++) {
        mrow[r] = -1e30f; lrow[r] = 0.0f;
        O2[r][0] = 0ull; O2[r][1] = 0ull;
    }

    int cur = 0;
    for (int t = 0; t <= qi; t++) {
        const int j0 = i0 - 64 * t;
        __syncthreads();

        {
            const float* ksrc = K + ((size_t)(b * LL + j0 + lr) * DD + h * DHH);
            const float* vsrc = V + ((size_t)(b * LL + j0 + lr) * DD + h * DHH);
            const int d = 64 * t + lr;
            const float* fsrc = rel + ((size_t)(LL - 1 - d) * DD + h * DHH);
#pragma unroll
            for (int it = 0; it < 4; it++) {
                int f = lq4 + 4 * it;
                float4 kv = *(const float4*)(ksrc + 4 * f);
                Ks[(4 * f + 0) * ATS + lr] = kv.x;
                Ks[(4 * f + 1) * ATS + lr] = kv.y;
                Ks[(4 * f + 2) * ATS + lr] = kv.z;
                Ks[(4 * f + 3) * ATS + lr] = kv.w;
                float4 fv = *(const float4*)(fsrc + 4 * f);
                FPs[(4 * f + 0) * ATS + lr] = fv.x;
                FPs[(4 * f + 1) * ATS + lr] = fv.y;
                FPs[(4 * f + 2) * ATS + lr] = fv.z;
                FPs[(4 * f + 3) * ATS + lr] = fv.w;
                float4 vv = *(const float4*)(vsrc + 4 * f);
                *(float4*)&Vs[lr * ATS + 4 * f] = vv;
            }
        }
        __syncthreads();

        u64 s2[4][2], rn2[4][2];
#pragma unroll
        for (int r = 0; r < 4; r++) {
            s2[r][0] = s2[r][1] = 0ull;
            rn2[r][0] = rn2[r][1] = 0ull;
        }

#pragma unroll 8
        for (int kk = 0; kk < 64; kk++) {
            float4 qv = *(const float4*)&Qs[kk * ATS + 4 * ty];
            ulonglong2 kp = *(const ulonglong2*)&Ks[kk * ATS + 4 * tx];
            ulonglong2 fp = *(const ulonglong2*)&FPs[kk * ATS + 4 * tx];
            float qa[4] = {qv.x, qv.y, qv.z, qv.w};
#pragma unroll
            for (int r = 0; r < 4; r++) {
                u64 qd = dup2(qa[r]);
                fma2(s2[r][0], qd, kp.x);
                fma2(s2[r][1], qd, kp.y);
                fma2(rn2[r][0], qd, fp.x);
                fma2(rn2[r][1], qd, fp.y);
            }
        }

        float s[4][4], rn[4][4];
#pragma unroll
        for (int r = 0; r < 4; r++) {
            float2 v0 = unpk2(s2[r][0]);  float2 v1 = unpk2(s2[r][1]);
            s[r][0] = v0.x; s[r][1] = v0.y; s[r][2] = v1.x; s[r][3] = v1.y;
            float2 w0 = unpk2(rn2[r][0]); float2 w1 = unpk2(rn2[r][1]);
            rn[r][0] = w0.x; rn[r][1] = w0.y; rn[r][2] = w1.x; rn[r][3] = w1.y;
        }

        float* Rc = cur ? Rs1 : Rs0;
        float* Rp = cur ? Rs0 : Rs1;
#pragma unroll
        for (int r = 0; r < 4; r++)
#pragma unroll
            for (int c = 0; c < 4; c++)
                Rc[(4 * ty + r) * ATS + 4 * tx + c] = rn[r][c];
        __syncthreads();

        float mx[4];
#pragma unroll
        for (int r = 0; r < 4; r++) {
            const int di = 4 * ty + r;
            float rowm = -1e30f;
#pragma unroll
            for (int c = 0; c < 4; c++) {
                const int dj = 4 * tx + c;
                const int diff = di - dj;
                float relv = (diff >= 0) ? Rc[di * ATS + diff]
                                         : Rp[di * ATS + 64 + diff];
                float sv = (s[r][c] + relv) * scale;
                if (t == 0 && diff < 0) sv = -1e30f;
                s[r][c] = sv;
                rowm = fmaxf(rowm, sv);
            }
            rowm = fmaxf(rowm, __shfl_xor_sync(0xffffffffu, rowm, 8));
            rowm = fmaxf(rowm, __shfl_xor_sync(0xffffffffu, rowm, 4));
            rowm = fmaxf(rowm, __shfl_xor_sync(0xffffffffu, rowm, 2));
            rowm = fmaxf(rowm, __shfl_xor_sync(0xffffffffu, rowm, 1));
            mx[r] = rowm;
        }

#pragma unroll
        for (int r = 0; r < 4; r++) {
            const int di = 4 * ty + r;
            const float mnew = fmaxf(mrow[r], mx[r]);
            const float alpha = __expf(mrow[r] - mnew);
            mrow[r] = mnew;
            float rsum = 0.0f;
#pragma unroll
            for (int c = 0; c < 4; c++) {
                float e = __expf(s[r][c] - mnew);
                rsum += e;
                FPs[di * ATS + 4 * tx + c] = e;
            }
            rsum += __shfl_xor_sync(0xffffffffu, rsum, 8);
            rsum += __shfl_xor_sync(0xffffffffu, rsum, 4);
            rsum += __shfl_xor_sync(0xffffffffu, rsum, 2);
            rsum += __shfl_xor_sync(0xffffffffu, rsum, 1);
            lrow[r] = lrow[r] * alpha + rsum;
            u64 ad = dup2(alpha);
            O2[r][0] = mul2(O2[r][0], ad);
            O2[r][1] = mul2(O2[r][1], ad);
        }
        __syncthreads();

#pragma unroll 8
        for (int dj = 0; dj < 64; dj++) {
            ulonglong2 vp = *(const ulonglong2*)&Vs[dj * ATS + 4 * tx];
#pragma unroll
            for (int r = 0; r < 4; r++) {
                u64 pd = dup2(FPs[(4 * ty + r) * ATS + dj]);
                fma2(O2[r][0], pd, vp.x);
                fma2(O2[r][1], pd, vp.y);
            }
        }
        cur ^= 1;
    }

#pragma unroll
    for (int r = 0; r < 4; r++) {
        const int di = 4 * ty + r;
        const float inv = 1.0f / lrow[r];
        float2 v0 = unpk2(O2[r][0]);
        float2 v1 = unpk2(O2[r][1]);
        float out[4] = {v0.x * inv, v0.y * inv, v1.x * inv, v1.y * inv};
        float* dst = Out + ((size_t)(b * LL + i0 + di) * DD + h * DHH + 4 * tx);
        *(float4*)dst = *(float4*)&out[0];
    }
}

// ---------------------------------------------------------------------------
// Launch
// ---------------------------------------------------------------------------
extern "C" void kernel_launch(void* const* d_in, const int* in_sizes, int n_in,
                              void* d_out, int out_size)
{
    const float* x   = (const float*)d_in[0];
    // d_in[1] = mask — handled analytically
    const float* wq  = (const float*)d_in[2];
    const float* bq  = (const float*)d_in[3];
    const float* wk  = (const float*)d_in[4];
    const float* bk  = (const float*)d_in[5];
    const float* wv  = (const float*)d_in[6];
    const float* bv  = (const float*)d_in[7];
    const float* rel = (const float*)d_in[8];
    const float* w1  = (const float*)d_in[9];
    const float* b1  = (const float*)d_in[10];
    const float* w2  = (const float*)d_in[11];
    const float* b2  = (const float*)d_in[12];
    float* out = (float*)d_out;

    float *Qp, *Kp, *Vp, *Ap;
    __nv_bfloat16 *xh, *xl, *ah, *al, *hh, *hl;
    __nv_bfloat16 *wqh, *wql, *wkh, *wkl, *wvh, *wvl, *w1h, *w1l, *w2h, *w2l;
    cudaGetSymbolAddress((void**)&Qp, g_Q);
    cudaGetSymbolAddress((void**)&Kp, g_K);
    cudaGetSymbolAddress((void**)&Vp, g_V);
    cudaGetSymbolAddress((void**)&Ap, g_A);
    cudaGetSymbolAddress((void**)&xh, g_xh);  cudaGetSymbolAddress((void**)&xl, g_xl);
    cudaGetSymbolAddress((void**)&ah, g_ah);  cudaGetSymbolAddress((void**)&al, g_al);
    cudaGetSymbolAddress((void**)&hh, g_hh);  cudaGetSymbolAddress((void**)&hl, g_hl);
    cudaGetSymbolAddress((void**)&wqh, g_wqh); cudaGetSymbolAddress((void**)&wql, g_wql);
    cudaGetSymbolAddress((void**)&wkh, g_wkh); cudaGetSymbolAddress((void**)&wkl, g_wkl);
    cudaGetSymbolAddress((void**)&wvh, g_wvh); cudaGetSymbolAddress((void**)&wvl, g_wvl);
    cudaGetSymbolAddress((void**)&w1h, g_w1h); cudaGetSymbolAddress((void**)&w1l, g_w1l);
    cudaGetSymbolAddress((void**)&w2h, g_w2h); cudaGetSymbolAddress((void**)&w2l, g_w2l);

    cudaFuncSetAttribute(tgemm_kernel<0>, cudaFuncAttributeMaxDynamicSharedMemorySize, TG_SMEM);
    cudaFuncSetAttribute(tgemm_kernel<1>, cudaFuncAttributeMaxDynamicSharedMemorySize, TG_SMEM);

    // 0) Input/weight preparation (split + transpose)
    convert_split_kernel<<<(MM * DD / 4 + 255) / 256, 256>>>((const float4*)x, xh, xl, MM * DD / 4);
    transpose_split_kernel<<<dim3(DD / 32,   DD / 32),   256>>>(wq, wqh, wql, DD,   DD);
    transpose_split_kernel<<<dim3(DD / 32,   DD / 32),   256>>>(wk, wkh, wkl, DD,   DD);
    transpose_split_kernel<<<dim3(DD / 32,   DD / 32),   256>>>(wv, wvh, wvl, DD,   DD);
    transpose_split_kernel<<<dim3(DFCN / 32, DD / 32),   256>>>(w1, w1h, w1l, DD,   DFCN);
    transpose_split_kernel<<<dim3(DD / 32,   DFCN / 32), 256>>>(w2, w2h, w2l, DFCN, DD);

    // 1) QKV projections (tensor-core split-bf16 GEMM)
    tgemm_kernel<0><<<dim3(DD / 128, MM / 128), 256, TG_SMEM>>>(
        xh, xl, wqh, wql, bq, Qp, nullptr, nullptr, MM, DD, DD);
    tgemm_kernel<0><<<dim3(DD / 128, MM / 128), 256, TG_SMEM>>>(
        xh, xl, wkh, wkl, bk, Kp, nullptr, nullptr, MM, DD, DD);
    tgemm_kernel<0><<<dim3(DD / 128, MM / 128), 256, TG_SMEM>>>(
        xh, xl, wvh, wvl, bv, Vp, nullptr, nullptr, MM, DD, DD);

    // 2) Flash attention with relative bias
    const size_t attn_smem = 6 * 64 * ATS * sizeof(float);
    cudaFuncSetAttribute(attn_kernel, cudaFuncAttributeMaxDynamicSharedMemorySize,
                         (int)attn_smem);
    attn_kernel<<<dim3(LL / 64, HH, BB), 256, attn_smem>>>(Qp, Kp, Vp, rel, Ap);

    // 3) Split attention output, FFN1 (ReLU, split bf16 out), FFN2 (fp32 out)
    convert_split_kernel<<<(MM * DD / 4 + 255) / 256, 256>>>((const float4*)Ap, ah, al, MM * DD / 4);
    tgemm_kernel<1><<<dim3(DFCN / 128, MM / 128), 256, TG_SMEM>>>(
        ah, al, w1h, w1l, b1, nullptr, hh, hl, MM, DFCN, DD);
    tgemm_kernel<0><<<dim3(DD / 128, MM / 128), 256, TG_SMEM>>>(
        hh, hl, w2h, w2l, b2, out, nullptr, nullptr, MM, DD, DFCN);
}

// round 7
// speedup vs baseline: 1.4893x; 1.0191x over previous
#include <cuda_runtime.h>
#include <cuda_bf16.h>
#include <cstdint>
#include <cstddef>

// ---------------------------------------------------------------------------
// Problem constants
// ---------------------------------------------------------------------------
#define BB   2
#define LL   2048
#define DD   512
#define HH   8
#define DHH  64
#define DFCN 2048
#define MM   (BB * LL)        // 4096 rows

typedef unsigned long long u64;
typedef unsigned int u32;

// ---------------------------------------------------------------------------
// Scratch (device globals: allocation-guard-safe)
// ---------------------------------------------------------------------------
__device__ float g_Q[MM * DD];
__device__ float g_K[MM * DD];
__device__ float g_V[MM * DD];
__device__ float g_A[MM * DD];                 // attention output (B,L,D) fp32

__device__ __nv_bfloat16 g_xh[MM * DD],   g_xl[MM * DD];      // split x
__device__ __nv_bfloat16 g_ah[MM * DD],   g_al[MM * DD];      // split attn out
__device__ __nv_bfloat16 g_hh[MM * DFCN], g_hl[MM * DFCN];    // split FFN hidden

// Transposed + split weights: T[n][k] = W[k][n]
__device__ __nv_bfloat16 g_wqh[DD * DD],   g_wql[DD * DD];
__device__ __nv_bfloat16 g_wkh[DD * DD],   g_wkl[DD * DD];
__device__ __nv_bfloat16 g_wvh[DD * DD],   g_wvl[DD * DD];
__device__ __nv_bfloat16 g_w1h[DFCN * DD], g_w1l[DFCN * DD];  // [2048][512]
__device__ __nv_bfloat16 g_w2h[DD * DFCN], g_w2l[DD * DFCN];  // [512][2048]

// ---------------------------------------------------------------------------
// Helpers
// ---------------------------------------------------------------------------
__device__ __forceinline__ u32 smem_u32(const void* p) {
    u32 a;
    asm("{ .reg .u64 t; cvta.to.shared.u64 t, %1; cvt.u32.u64 %0, t; }"
        : "=r"(a) : "l"(p));
    return a;
}

__device__ __forceinline__ u32 pack_bf2(__nv_bfloat16 a, __nv_bfloat16 b) {
    return (u32)__bfloat16_as_ushort(a) | ((u32)__bfloat16_as_ushort(b) << 16);
}

#define LDSM_X4(r, addr) \
    asm volatile("ldmatrix.sync.aligned.m8n8.x4.shared.b16 {%0,%1,%2,%3}, [%4];" \
        : "=r"((r)[0]), "=r"((r)[1]), "=r"((r)[2]), "=r"((r)[3]) : "r"(addr))

#define MMA_BF16(d, a, b0, b1) \
    asm volatile("mma.sync.aligned.m16n8k16.row.col.f32.bf16.bf16.f32 " \
        "{%0,%1,%2,%3}, {%4,%5,%6,%7}, {%8,%9}, {%0,%1,%2,%3};" \
        : "+f"((d)[0]), "+f"((d)[1]), "+f"((d)[2]), "+f"((d)[3]) \
        : "r"((a)[0]), "r"((a)[1]), "r"((a)[2]), "r"((a)[3]), "r"(b0), "r"(b1))

__device__ __forceinline__ void cp16(u32 dst, const void* src) {
    asm volatile("cp.async.cg.shared.global [%0], [%1], 16;"
                 :: "r"(dst), "l"(src) : "memory");
}
#define CP_COMMIT()  asm volatile("cp.async.commit_group;" ::: "memory")
#define CP_WAIT(n)   asm volatile("cp.async.wait_group %0;" :: "n"(n) : "memory")

// ---------------------------------------------------------------------------
// Weight transpose + bf16 split: W[K][N] fp32 -> Th/Tl[N][K] bf16
// ---------------------------------------------------------------------------
__global__ __launch_bounds__(256)
void transpose_split_kernel(const float* __restrict__ W,
                            __nv_bfloat16* __restrict__ Th,
                            __nv_bfloat16* __restrict__ Tl,
                            int K, int N)
{
    __shared__ float t[32][33];
    const int n0 = blockIdx.x * 32, k0 = blockIdx.y * 32;
    const int tx = threadIdx.x & 31, ty = threadIdx.x >> 5;   // ty 0..7
#pragma unroll
    for (int i = 0; i < 4; i++) {
        int k = k0 + ty + 8 * i;
        t[ty + 8 * i][tx] = W[(size_t)k * N + n0 + tx];
    }
    __syncthreads();
#pragma unroll
    for (int i = 0; i < 4; i++) {
        int n = n0 + ty + 8 * i;
        float v = t[tx][ty + 8 * i];
        __nv_bfloat16 h = __float2bfloat16(v);
        float r = v - __bfloat162float(h);
        Th[(size_t)n * K + k0 + tx] = h;
        Tl[(size_t)n * K + k0 + tx] = __float2bfloat16(r);
    }
}

// ---------------------------------------------------------------------------
// Elementwise bf16 split of an fp32 tensor (row-major preserved)
// ---------------------------------------------------------------------------
__global__ __launch_bounds__(256)
void convert_split_kernel(const float4* __restrict__ X,
                          __nv_bfloat16* __restrict__ H,
                          __nv_bfloat16* __restrict__ L, int n4)
{
    int i = blockIdx.x * blockDim.x + threadIdx.x;
    if (i >= n4) return;
    float4 v = X[i];
    __nv_bfloat16 h0 = __float2bfloat16(v.x), h1 = __float2bfloat16(v.y);
    __nv_bfloat16 h2 = __float2bfloat16(v.z), h3 = __float2bfloat16(v.w);
    uint2 hp, lp;
    hp.x = pack_bf2(h0, h1); hp.y = pack_bf2(h2, h3);
    lp.x = pack_bf2(__float2bfloat16(v.x - __bfloat162float(h0)),
                    __float2bfloat16(v.y - __bfloat162float(h1)));
    lp.y = pack_bf2(__float2bfloat16(v.z - __bfloat162float(h2)),
                    __float2bfloat16(v.w - __bfloat162float(h3)));
    *(uint2*)(H + 4 * (size_t)i) = hp;
    *(uint2*)(L + 4 * (size_t)i) = lp;
}

// ---------------------------------------------------------------------------
// Tensor-core split-bf16 GEMM via mma.sync (HMMA, works on plain sm_103):
//   C = A @ B^T + bias, A as (Ah,Al) [M][K], B as (Bh,Bl) [N][K], all bf16.
//   fp32 register accumulation: D = Ah·Bh + Ah·Bl + Al·Bh.
// 128x128x32 CTA tile, 8 warps (2x4), 64x32 warp tile, cp.async double buffer.
// Smem: 64B rows (32 bf16), 16B chunk swizzle c ^= (row>>1)&3 (ldmatrix
// conflict-free). MODE 0: Cf = D + bias fp32. MODE 1: relu split -> (Ch, Cl).
// ---------------------------------------------------------------------------
#define TG_TILE_BYTES  8192            // 128 x 32 x 2B
#define TG_STAGE_BYTES 32768           // Ah, Al, Bh, Bl
#define TG_SMEM        (2 * TG_STAGE_BYTES)

__device__ __forceinline__ void load_tile_cp(const __nv_bfloat16* __restrict__ src,
                                             int ldk, u32 sdst, int tid)
{
    // 128 rows x 4 16B chunks = 512 chunk loads, 256 threads x 2
#pragma unroll
    for (int i = 0; i < 2; i++) {
        int idx = tid + 256 * i;
        int r = idx >> 2, c = idx & 3;
        u32 dst = sdst + r * 64 + 16 * (c ^ ((r >> 1) & 3));
        cp16(dst, src + (size_t)r * ldk + 8 * c);
    }
}

template <int MODE>
__global__ __launch_bounds__(256, 1)
void tgemm_kernel(const __nv_bfloat16* __restrict__ Ah,
                  const __nv_bfloat16* __restrict__ Al,
                  const __nv_bfloat16* __restrict__ Bh,
                  const __nv_bfloat16* __restrict__ Bl,
                  const float* __restrict__ bias,
                  float* __restrict__ Cf,
                  __nv_bfloat16* __restrict__ Ch,
                  __nv_bfloat16* __restrict__ Cl,
                  int M, int N, int K)
{
    extern __shared__ char smem[];
    const u32 sb = smem_u32(smem);
    const int tid  = threadIdx.x;
    const int wid  = tid >> 5, lane = tid & 31;
    const int wm   = wid >> 2, wn = wid & 3;        // 2 x 4 warp grid
    const int m0   = blockIdx.y * 128;
    const int n0   = blockIdx.x * 128;
    const int NC   = K >> 5;                        // chunks of BK=32

    float acc[4][4][4];
#pragma unroll
    for (int mt = 0; mt < 4; mt++)
#pragma unroll
        for (int nt = 0; nt < 4; nt++)
#pragma unroll
            for (int r = 0; r < 4; r++) acc[mt][nt][r] = 0.0f;

    const __nv_bfloat16* Abase_h = Ah + (size_t)m0 * K;
    const __nv_bfloat16* Abase_l = Al + (size_t)m0 * K;
    const __nv_bfloat16* Bbase_h = Bh + (size_t)n0 * K;
    const __nv_bfloat16* Bbase_l = Bl + (size_t)n0 * K;

    // prologue: stage 0
    {
        u32 base = sb;
        load_tile_cp(Abase_h, K, base,                     tid);
        load_tile_cp(Abase_l, K, base + TG_TILE_BYTES,     tid);
        load_tile_cp(Bbase_h, K, base + 2 * TG_TILE_BYTES, tid);
        load_tile_cp(Bbase_l, K, base + 3 * TG_TILE_BYTES, tid);
        CP_COMMIT();
    }

    // Precompute ldmatrix lane row/chunk components
    const int lrow  = lane & 15;          // row within 16-row group
    const int lcol  = lane >> 4;          // chunk phase 0/1

    for (int c = 0; c < NC; c++) {
        if (c + 1 < NC) {
            u32 base = sb + ((c + 1) & 1) * TG_STAGE_BYTES;
            const int kofs = (c + 1) * 32;
            load_tile_cp(Abase_h + kofs, K, base,                     tid);
            load_tile_cp(Abase_l + kofs, K, base + TG_TILE_BYTES,     tid);
            load_tile_cp(Bbase_h + kofs, K, base + 2 * TG_TILE_BYTES, tid);
            load_tile_cp(Bbase_l + kofs, K, base + 3 * TG_TILE_BYTES, tid);
            CP_COMMIT();
            CP_WAIT(1);
        } else {
            CP_WAIT(0);
        }
        __syncthreads();

        const u32 base = sb + (c & 1) * TG_STAGE_BYTES;
        const u32 sAh = base;
        const u32 sAl = base + TG_TILE_BYTES;
        const u32 sBh = base + 2 * TG_TILE_BYTES;
        const u32 sBl = base + 3 * TG_TILE_BYTES;

#pragma unroll
        for (int ks = 0; ks < 2; ks++) {
            u32 ah[4][4], al[4][4], bh[2][4], bl[2][4];
#pragma unroll
            for (int mt = 0; mt < 4; mt++) {
                int r  = wm * 64 + mt * 16 + lrow;
                int ch = 2 * ks + lcol;
                u32 off = r * 64 + 16 * (ch ^ ((r >> 1) & 3));
                LDSM_X4(ah[mt], sAh + off);
                LDSM_X4(al[mt], sAl + off);
            }
#pragma unroll
            for (int ng = 0; ng < 2; ng++) {
                int r  = wn * 32 + ng * 16 + lrow;
                int ch = 2 * ks + lcol;
                u32 off = r * 64 + 16 * (ch ^ ((r >> 1) & 3));
                LDSM_X4(bh[ng], sBh + off);
                LDSM_X4(bl[ng], sBl + off);
            }
#pragma unroll
            for (int mt = 0; mt < 4; mt++)
#pragma unroll
                for (int nt = 0; nt < 4; nt++) {
                    const int ng = nt >> 1, hi = nt & 1;
                    MMA_BF16(acc[mt][nt], ah[mt], bh[ng][hi], bh[ng][2 + hi]);
                    MMA_BF16(acc[mt][nt], ah[mt], bl[ng][hi], bl[ng][2 + hi]);
                    MMA_BF16(acc[mt][nt], al[mt], bh[ng][hi], bh[ng][2 + hi]);
                }
        }
        __syncthreads();
    }

    // Epilogue: D frag thread map — rows t/4 (+8), cols 2*(t%4) (+1)
    const int tg = lane >> 2;
    const int tc = (lane & 3) * 2;
#pragma unroll
    for (int mt = 0; mt < 4; mt++) {
#pragma unroll
        for (int half = 0; half < 2; half++) {
            const int m = m0 + wm * 64 + mt * 16 + tg + 8 * half;
#pragma unroll
            for (int nt = 0; nt < 4; nt++) {
                const int n = n0 + wn * 32 + nt * 8 + tc;
                float v0 = acc[mt][nt][2 * half]     + bias[n];
                float v1 = acc[mt][nt][2 * half + 1] + bias[n + 1];
                if (MODE == 0) {
                    float2 o = make_float2(v0, v1);
                    *(float2*)(Cf + (size_t)m * N + n) = o;
                } else {
                    v0 = fmaxf(v0, 0.0f);
                    v1 = fmaxf(v1, 0.0f);
                    __nv_bfloat16 h0 = __float2bfloat16(v0);
                    __nv_bfloat16 h1 = __float2bfloat16(v1);
                    __nv_bfloat16 l0 = __float2bfloat16(v0 - __bfloat162float(h0));
                    __nv_bfloat16 l1 = __float2bfloat16(v1 - __bfloat162float(h1));
                    *(u32*)(Ch + (size_t)m * N + n) = pack_bf2(h0, h1);
                    *(u32*)(Cl + (size_t)m * N + n) = pack_bf2(l0, l1);
                }
            }
        }
    }
}

// ---------------------------------------------------------------------------
// Flash attention with relative position bias (round-3 version, FFMA2 path).
//   logits[i,j] = (Q_i.K_j + Q_i.rel_emb[2047-(i-j)]) / 8   for j <= i
// ---------------------------------------------------------------------------
__device__ __forceinline__ u64 dup2(float x) {
    u64 r; asm("mov.b64 %0, {%1, %1};" : "=l"(r) : "f"(x)); return r;
}
__device__ __forceinline__ void fma2(u64& d, u64 a, u64 b) {
    asm("fma.rn.f32x2 %0, %1, %2, %0;" : "+l"(d) : "l"(a), "l"(b));
}
__device__ __forceinline__ u64 mul2(u64 a, u64 b) {
    u64 r; asm("mul.rn.f32x2 %0, %1, %2;" : "=l"(r) : "l"(a), "l"(b)); return r;
}
__device__ __forceinline__ float2 unpk2(u64 v) {
    float2 f; asm("mov.b64 {%0, %1}, %2;" : "=f"(f.x), "=f"(f.y) : "l"(v)); return f;
}

#define ATS 68

__global__ __launch_bounds__(256, 2)
void attn_kernel(const float* __restrict__ Q, const float* __restrict__ K,
                 const float* __restrict__ V, const float* __restrict__ rel,
                 float* __restrict__ Out)
{
    extern __shared__ float sm[];
    float* Qs  = sm;
    float* Ks  = sm + 1 * 64 * ATS;
    float* Vs  = sm + 2 * 64 * ATS;
    float* FPs = sm + 3 * 64 * ATS;
    float* Rs0 = sm + 4 * 64 * ATS;
    float* Rs1 = sm + 5 * 64 * ATS;

    const int qi = blockIdx.x;
    const int h  = blockIdx.y;
    const int b  = blockIdx.z;
    const int i0 = qi * 64;
    const int tid = threadIdx.x;
    const int tx = tid & 15;
    const int ty = tid >> 4;
    const float scale = 0.125f;

    const int lr  = tid >> 2;
    const int lq4 = tid & 3;

    {
        const float* src = Q + ((size_t)(b * LL + i0 + lr) * DD + h * DHH);
#pragma unroll
        for (int it = 0; it < 4; it++) {
            int f = lq4 + 4 * it;
            float4 v = *(const float4*)(src + 4 * f);
            Qs[(4 * f + 0) * ATS + lr] = v.x;
            Qs[(4 * f + 1) * ATS + lr] = v.y;
            Qs[(4 * f + 2) * ATS + lr] = v.z;
            Qs[(4 * f + 3) * ATS + lr] = v.w;
        }
    }

    u64 O2[4][2];
    float mrow[4], lrow[4];
#pragma unroll
    for (int r = 0; r < 4; r++) {
        mrow[r] = -1e30f; lrow[r] = 0.0f;
        O2[r][0] = 0ull; O2[r][1] = 0ull;
    }

    int cur = 0;
    for (int t = 0; t <= qi; t++) {
        const int j0 = i0 - 64 * t;
        __syncthreads();

        {
            const float* ksrc = K + ((size_t)(b * LL + j0 + lr) * DD + h * DHH);
            const float* vsrc = V + ((size_t)(b * LL + j0 + lr) * DD + h * DHH);
            const int d = 64 * t + lr;
            const float* fsrc = rel + ((size_t)(LL - 1 - d) * DD + h * DHH);
#pragma unroll
            for (int it = 0; it < 4; it++) {
                int f = lq4 + 4 * it;
                float4 kv = *(const float4*)(ksrc + 4 * f);
                Ks[(4 * f + 0) * ATS + lr] = kv.x;
                Ks[(4 * f + 1) * ATS + lr] = kv.y;
                Ks[(4 * f + 2) * ATS + lr] = kv.z;
                Ks[(4 * f + 3) * ATS + lr] = kv.w;
                float4 fv = *(const float4*)(fsrc + 4 * f);
                FPs[(4 * f + 0) * ATS + lr] = fv.x;
                FPs[(4 * f + 1) * ATS + lr] = fv.y;
                FPs[(4 * f + 2) * ATS + lr] = fv.z;
                FPs[(4 * f + 3) * ATS + lr] = fv.w;
                float4 vv = *(const float4*)(vsrc + 4 * f);
                *(float4*)&Vs[lr * ATS + 4 * f] = vv;
            }
        }
        __syncthreads();

        u64 s2[4][2], rn2[4][2];
#pragma unroll
        for (int r = 0; r < 4; r++) {
            s2[r][0] = s2[r][1] = 0ull;
            rn2[r][0] = rn2[r][1] = 0ull;
        }

#pragma unroll 8
        for (int kk = 0; kk < 64; kk++) {
            float4 qv = *(const float4*)&Qs[kk * ATS + 4 * ty];
            ulonglong2 kp = *(const ulonglong2*)&Ks[kk * ATS + 4 * tx];
            ulonglong2 fp = *(const ulonglong2*)&FPs[kk * ATS + 4 * tx];
            float qa[4] = {qv.x, qv.y, qv.z, qv.w};
#pragma unroll
            for (int r = 0; r < 4; r++) {
                u64 qd = dup2(qa[r]);
                fma2(s2[r][0], qd, kp.x);
                fma2(s2[r][1], qd, kp.y);
                fma2(rn2[r][0], qd, fp.x);
                fma2(rn2[r][1], qd, fp.y);
            }
        }

        float s[4][4], rn[4][4];
#pragma unroll
        for (int r = 0; r < 4; r++) {
            float2 v0 = unpk2(s2[r][0]);  float2 v1 = unpk2(s2[r][1]);
            s[r][0] = v0.x; s[r][1] = v0.y; s[r][2] = v1.x; s[r][3] = v1.y;
            float2 w0 = unpk2(rn2[r][0]); float2 w1 = unpk2(rn2[r][1]);
            rn[r][0] = w0.x; rn[r][1] = w0.y; rn[r][2] = w1.x; rn[r][3] = w1.y;
        }

        float* Rc = cur ? Rs1 : Rs0;
        float* Rp = cur ? Rs0 : Rs1;
#pragma unroll
        for (int r = 0; r < 4; r++)
#pragma unroll
            for (int c = 0; c < 4; c++)
                Rc[(4 * ty + r) * ATS + 4 * tx + c] = rn[r][c];
        __syncthreads();

        float mx[4];
#pragma unroll
        for (int r = 0; r < 4; r++) {
            const int di = 4 * ty + r;
            float rowm = -1e30f;
#pragma unroll
            for (int c = 0; c < 4; c++) {
                const int dj = 4 * tx + c;
                const int diff = di - dj;
                float relv = (diff >= 0) ? Rc[di * ATS + diff]
                                         : Rp[di * ATS + 64 + diff];
                float sv = (s[r][c] + relv) * scale;
                if (t == 0 && diff < 0) sv = -1e30f;
                s[r][c] = sv;
                rowm = fmaxf(rowm, sv);
            }
            rowm = fmaxf(rowm, __shfl_xor_sync(0xffffffffu, rowm, 8));
            rowm = fmaxf(rowm, __shfl_xor_sync(0xffffffffu, rowm, 4));
            rowm = fmaxf(rowm, __shfl_xor_sync(0xffffffffu, rowm, 2));
            rowm = fmaxf(rowm, __shfl_xor_sync(0xffffffffu, rowm, 1));
            mx[r] = rowm;
        }

#pragma unroll
        for (int r = 0; r < 4; r++) {
            const int di = 4 * ty + r;
            const float mnew = fmaxf(mrow[r], mx[r]);
            const float alpha = __expf(mrow[r] - mnew);
            mrow[r] = mnew;
            float rsum = 0.0f;
#pragma unroll
            for (int c = 0; c < 4; c++) {
                float e = __expf(s[r][c] - mnew);
                rsum += e;
                FPs[di * ATS + 4 * tx + c] = e;
            }
            rsum += __shfl_xor_sync(0xffffffffu, rsum, 8);
            rsum += __shfl_xor_sync(0xffffffffu, rsum, 4);
            rsum += __shfl_xor_sync(0xffffffffu, rsum, 2);
            rsum += __shfl_xor_sync(0xffffffffu, rsum, 1);
            lrow[r] = lrow[r] * alpha + rsum;
            u64 ad = dup2(alpha);
            O2[r][0] = mul2(O2[r][0], ad);
            O2[r][1] = mul2(O2[r][1], ad);
        }
        __syncthreads();

#pragma unroll 8
        for (int dj = 0; dj < 64; dj++) {
            ulonglong2 vp = *(const ulonglong2*)&Vs[dj * ATS + 4 * tx];
#pragma unroll
            for (int r = 0; r < 4; r++) {
                u64 pd = dup2(FPs[(4 * ty + r) * ATS + dj]);
                fma2(O2[r][0], pd, vp.x);
                fma2(O2[r][1], pd, vp.y);
            }
        }
        cur ^= 1;
    }

#pragma unroll
    for (int r = 0; r < 4; r++) {
        const int di = 4 * ty + r;
        const float inv = 1.0f / lrow[r];
        float2 v0 = unpk2(O2[r][0]);
        float2 v1 = unpk2(O2[r][1]);
        float out[4] = {v0.x * inv, v0.y * inv, v1.x * inv, v1.y * inv};
        float* dst = Out + ((size_t)(b * LL + i0 + di) * DD + h * DHH + 4 * tx);
        *(float4*)dst = *(float4*)&out[0];
    }
}

// ---------------------------------------------------------------------------
// Launch
// ---------------------------------------------------------------------------
extern "C" void kernel_launch(void* const* d_in, const int* in_sizes, int n_in,
                              void* d_out, int out_size)
{
    const float* x   = (const float*)d_in[0];
    // d_in[1] = mask — handled analytically
    const float* wq  = (const float*)d_in[2];
    const float* bq  = (const float*)d_in[3];
    const float* wk  = (const float*)d_in[4];
    const float* bk  = (const float*)d_in[5];
    const float* wv  = (const float*)d_in[6];
    const float* bv  = (const float*)d_in[7];
    const float* rel = (const float*)d_in[8];
    const float* w1  = (const float*)d_in[9];
    const float* b1  = (const float*)d_in[10];
    const float* w2  = (const float*)d_in[11];
    const float* b2  = (const float*)d_in[12];
    float* out = (float*)d_out;

    float *Qp, *Kp, *Vp, *Ap;
    __nv_bfloat16 *xh, *xl, *ah, *al, *hh, *hl;
    __nv_bfloat16 *wqh, *wql, *wkh, *wkl, *wvh, *wvl, *w1h, *w1l, *w2h, *w2l;
    cudaGetSymbolAddress((void**)&Qp, g_Q);
    cudaGetSymbolAddress((void**)&Kp, g_K);
    cudaGetSymbolAddress((void**)&Vp, g_V);
    cudaGetSymbolAddress((void**)&Ap, g_A);
    cudaGetSymbolAddress((void**)&xh, g_xh);  cudaGetSymbolAddress((void**)&xl, g_xl);
    cudaGetSymbolAddress((void**)&ah, g_ah);  cudaGetSymbolAddress((void**)&al, g_al);
    cudaGetSymbolAddress((void**)&hh, g_hh);  cudaGetSymbolAddress((void**)&hl, g_hl);
    cudaGetSymbolAddress((void**)&wqh, g_wqh); cudaGetSymbolAddress((void**)&wql, g_wql);
    cudaGetSymbolAddress((void**)&wkh, g_wkh); cudaGetSymbolAddress((void**)&wkl, g_wkl);
    cudaGetSymbolAddress((void**)&wvh, g_wvh); cudaGetSymbolAddress((void**)&wvl, g_wvl);
    cudaGetSymbolAddress((void**)&w1h, g_w1h); cudaGetSymbolAddress((void**)&w1l, g_w1l);
    cudaGetSymbolAddress((void**)&w2h, g_w2h); cudaGetSymbolAddress((void**)&w2l, g_w2l);

    cudaFuncSetAttribute(tgemm_kernel<0>, cudaFuncAttributeMaxDynamicSharedMemorySize, TG_SMEM);
    cudaFuncSetAttribute(tgemm_kernel<1>, cudaFuncAttributeMaxDynamicSharedMemorySize, TG_SMEM);

    // 0) Input/weight preparation (split + transpose)
    convert_split_kernel<<<(MM * DD / 4 + 255) / 256, 256>>>((const float4*)x, xh, xl, MM * DD / 4);
    transpose_split_kernel<<<dim3(DD / 32,   DD / 32),   256>>>(wq, wqh, wql, DD,   DD);
    transpose_split_kernel<<<dim3(DD / 32,   DD / 32),   256>>>(wk, wkh, wkl, DD,   DD);
    transpose_split_kernel<<<dim3(DD / 32,   DD / 32),   256>>>(wv, wvh, wvl, DD,   DD);
    transpose_split_kernel<<<dim3(DFCN / 32, DD / 32),   256>>>(w1, w1h, w1l, DD,   DFCN);
    transpose_split_kernel<<<dim3(DD / 32,   DFCN / 32), 256>>>(w2, w2h, w2l, DFCN, DD);

    // 1) QKV projections (tensor-core split-bf16 GEMM)
    tgemm_kernel<0><<<dim3(DD / 128, MM / 128), 256, TG_SMEM>>>(
        xh, xl, wqh, wql, bq, Qp, nullptr, nullptr, MM, DD, DD);
    tgemm_kernel<0><<<dim3(DD / 128, MM / 128), 256, TG_SMEM>>>(
        xh, xl, wkh, wkl, bk, Kp, nullptr, nullptr, MM, DD, DD);
    tgemm_kernel<0><<<dim3(DD / 128, MM / 128), 256, TG_SMEM>>>(
        xh, xl, wvh, wvl, bv, Vp, nullptr, nullptr, MM, DD, DD);

    // 2) Flash attention with relative bias
    const size_t attn_smem = 6 * 64 * ATS * sizeof(float);
    cudaFuncSetAttribute(attn_kernel, cudaFuncAttributeMaxDynamicSharedMemorySize,
                         (int)attn_smem);
    attn_kernel<<<dim3(LL / 64, HH, BB), 256, attn_smem>>>(Qp, Kp, Vp, rel, Ap);

    // 3) Split attention output, FFN1 (ReLU, split bf16 out), FFN2 (fp32 out)
    convert_split_kernel<<<(MM * DD / 4 + 255) / 256, 256>>>((const float4*)Ap, ah, al, MM * DD / 4);
    tgemm_kernel<1><<<dim3(DFCN / 128, MM / 128), 256, TG_SMEM>>>(
        ah, al, w1h, w1l, b1, nullptr, hh, hl, MM, DFCN, DD);
    tgemm_kernel<0><<<dim3(DD / 128, MM / 128), 256, TG_SMEM>>>(
        hh, hl, w2h, w2l, b2, out, nullptr, nullptr, MM, DD, DFCN);
}

// round 8
// speedup vs baseline: 2.6430x; 1.7746x over previous
#include <cuda_runtime.h>
#include <cuda_bf16.h>
#include <cstdint>
#include <cstddef>

// ---------------------------------------------------------------------------
// Problem constants
// ---------------------------------------------------------------------------
#define BB   2
#define LL   2048
#define DD   512
#define HH   8
#define DHH  64
#define DFCN 2048
#define MM   (BB * LL)        // 4096 rows

typedef unsigned long long u64;
typedef unsigned int u32;

// ---------------------------------------------------------------------------
// Scratch (device globals: allocation-guard-safe)
// ---------------------------------------------------------------------------
__device__ float g_V[MM * DD];                                // V fp32 (pre-transpose)

__device__ __nv_bfloat16 g_xh[MM * DD],   g_xl[MM * DD];      // split x
__device__ __nv_bfloat16 g_qh[MM * DD],   g_ql[MM * DD];      // split scaled Q
__device__ __nv_bfloat16 g_kh[MM * DD],   g_kl[MM * DD];      // split K
__device__ __nv_bfloat16 g_vth[BB*HH*DHH * LL], g_vtl[BB*HH*DHH * LL]; // V^T split
__device__ __nv_bfloat16 g_relh[LL * DD], g_rell[LL * DD];    // split rel_emb
__device__ __nv_bfloat16 g_ah[MM * DD],   g_al[MM * DD];      // split attn out
__device__ __nv_bfloat16 g_hh[MM * DFCN], g_hl[MM * DFCN];    // split FFN hidden

// Transposed + split weights: T[n][k] = W[k][n]
__device__ __nv_bfloat16 g_wqh[DD * DD],   g_wql[DD * DD];
__device__ __nv_bfloat16 g_wkh[DD * DD],   g_wkl[DD * DD];
__device__ __nv_bfloat16 g_wvh[DD * DD],   g_wvl[DD * DD];
__device__ __nv_bfloat16 g_w1h[DFCN * DD], g_w1l[DFCN * DD];
__device__ __nv_bfloat16 g_w2h[DD * DFCN], g_w2l[DD * DFCN];

// ---------------------------------------------------------------------------
// Helpers
// ---------------------------------------------------------------------------
__device__ __forceinline__ u32 smem_u32(const void* p) {
    u32 a;
    asm("{ .reg .u64 t; cvta.to.shared.u64 t, %1; cvt.u32.u64 %0, t; }"
        : "=r"(a) : "l"(p));
    return a;
}

__device__ __forceinline__ u32 pack_bf2(__nv_bfloat16 a, __nv_bfloat16 b) {
    return (u32)__bfloat16_as_ushort(a) | ((u32)__bfloat16_as_ushort(b) << 16);
}

// split two floats into hi/lo bf16x2 packs
__device__ __forceinline__ void split2(float x, float y, u32& hp, u32& lp) {
    __nv_bfloat16 hx = __float2bfloat16(x), hy = __float2bfloat16(y);
    hp = pack_bf2(hx, hy);
    lp = pack_bf2(__float2bfloat16(x - __bfloat162float(hx)),
                  __float2bfloat16(y - __bfloat162float(hy)));
}

#define LDSM_X4(r, addr) \
    asm volatile("ldmatrix.sync.aligned.m8n8.x4.shared.b16 {%0,%1,%2,%3}, [%4];" \
        : "=r"((r)[0]), "=r"((r)[1]), "=r"((r)[2]), "=r"((r)[3]) : "r"(addr))

#define MMA_BF16(d, a, b0, b1) \
    asm volatile("mma.sync.aligned.m16n8k16.row.col.f32.bf16.bf16.f32 " \
        "{%0,%1,%2,%3}, {%4,%5,%6,%7}, {%8,%9}, {%0,%1,%2,%3};" \
        : "+f"((d)[0]), "+f"((d)[1]), "+f"((d)[2]), "+f"((d)[3]) \
        : "r"((a)[0]), "r"((a)[1]), "r"((a)[2]), "r"((a)[3]), "r"(b0), "r"(b1))

__device__ __forceinline__ void cp16(u32 dst, const void* src) {
    asm volatile("cp.async.cg.shared.global [%0], [%1], 16;"
                 :: "r"(dst), "l"(src) : "memory");
}
#define CP_COMMIT()  asm volatile("cp.async.commit_group;" ::: "memory")
#define CP_WAIT(n)   asm volatile("cp.async.wait_group %0;" :: "n"(n) : "memory")

// ---------------------------------------------------------------------------
// Weight transpose + bf16 split: W[K][N] fp32 -> Th/Tl[N][K] bf16
// ---------------------------------------------------------------------------
__global__ __launch_bounds__(256)
void transpose_split_kernel(const float* __restrict__ W,
                            __nv_bfloat16* __restrict__ Th,
                            __nv_bfloat16* __restrict__ Tl,
                            int K, int N)
{
    __shared__ float t[32][33];
    const int n0 = blockIdx.x * 32, k0 = blockIdx.y * 32;
    const int tx = threadIdx.x & 31, ty = threadIdx.x >> 5;
#pragma unroll
    for (int i = 0; i < 4; i++)
        t[ty + 8 * i][tx] = W[(size_t)(k0 + ty + 8 * i) * N + n0 + tx];
    __syncthreads();
#pragma unroll
    for (int i = 0; i < 4; i++) {
        int n = n0 + ty + 8 * i;
        float v = t[tx][ty + 8 * i];
        __nv_bfloat16 h = __float2bfloat16(v);
        Th[(size_t)n * K + k0 + tx] = h;
        Tl[(size_t)n * K + k0 + tx] = __float2bfloat16(v - __bfloat162float(h));
    }
}

// ---------------------------------------------------------------------------
// V transpose + split: g_V fp32 [B*L][512] -> Vt[b*512 + col][token in b] bf16
// ---------------------------------------------------------------------------
__global__ __launch_bounds__(256)
void vt_split_kernel(const float* __restrict__ V,
                     __nv_bfloat16* __restrict__ Th,
                     __nv_bfloat16* __restrict__ Tl)
{
    __shared__ float t[32][33];
    const int n0 = blockIdx.x * 32;      // col in [0,512)
    const int k0 = blockIdx.y * 32;      // token in [0,4096)
    const int b  = k0 >> 11;
    const int tx = threadIdx.x & 31, ty = threadIdx.x >> 5;
#pragma unroll
    for (int i = 0; i < 4; i++)
        t[ty + 8 * i][tx] = V[(size_t)(k0 + ty + 8 * i) * DD + n0 + tx];
    __syncthreads();
#pragma unroll
    for (int i = 0; i < 4; i++) {
        int n = n0 + ty + 8 * i;
        float v = t[tx][ty + 8 * i];     // = V[k0+tx][n]
        __nv_bfloat16 h = __float2bfloat16(v);
        size_t o = (size_t)(b * 512 + n) * LL + (k0 & 2047) + tx;
        Th[o] = h;
        Tl[o] = __float2bfloat16(v - __bfloat162float(h));
    }
}

// ---------------------------------------------------------------------------
// Elementwise bf16 split of an fp32 tensor (row-major preserved)
// ---------------------------------------------------------------------------
__global__ __launch_bounds__(256)
void convert_split_kernel(const float4* __restrict__ X,
                          __nv_bfloat16* __restrict__ H,
                          __nv_bfloat16* __restrict__ L, int n4)
{
    int i = blockIdx.x * blockDim.x + threadIdx.x;
    if (i >= n4) return;
    float4 v = X[i];
    u32 h0, l0, h1, l1;
    split2(v.x, v.y, h0, l0);
    split2(v.z, v.w, h1, l1);
    *(uint2*)(H + 4 * (size_t)i) = make_uint2(h0, h1);
    *(uint2*)(L + 4 * (size_t)i) = make_uint2(l0, l1);
}

// ---------------------------------------------------------------------------
// Tensor-core split-bf16 GEMM (mma.sync): C = A @ B^T + bias
// MODE 0: fp32 out. MODE 1: relu+split out. MODE 2: scale+split out.
// ---------------------------------------------------------------------------
#define TG_TILE_BYTES  8192
#define TG_STAGE_BYTES 32768
#define TG_SMEM        (2 * TG_STAGE_BYTES)

__device__ __forceinline__ void load_tile_cp(const __nv_bfloat16* __restrict__ src,
                                             int ldk, u32 sdst, int tid)
{
#pragma unroll
    for (int i = 0; i < 2; i++) {
        int idx = tid + 256 * i;
        int r = idx >> 2, c = idx & 3;
        u32 dst = sdst + r * 64 + 16 * (c ^ ((r >> 1) & 3));
        cp16(dst, src + (size_t)r * ldk + 8 * c);
    }
}

template <int MODE>
__global__ __launch_bounds__(256, 1)
void tgemm_kernel(const __nv_bfloat16* __restrict__ Ah,
                  const __nv_bfloat16* __restrict__ Al,
                  const __nv_bfloat16* __restrict__ Bh,
                  const __nv_bfloat16* __restrict__ Bl,
                  const float* __restrict__ bias,
                  float* __restrict__ Cf,
                  __nv_bfloat16* __restrict__ Ch,
                  __nv_bfloat16* __restrict__ Cl,
                  int M, int N, int K, float scl)
{
    extern __shared__ char smem[];
    const u32 sb = smem_u32(smem);
    const int tid  = threadIdx.x;
    const int wid  = tid >> 5, lane = tid & 31;
    const int wm   = wid >> 2, wn = wid & 3;
    const int m0   = blockIdx.y * 128;
    const int n0   = blockIdx.x * 128;
    const int NC   = K >> 5;

    float acc[4][4][4];
#pragma unroll
    for (int mt = 0; mt < 4; mt++)
#pragma unroll
        for (int nt = 0; nt < 4; nt++)
#pragma unroll
            for (int r = 0; r < 4; r++) acc[mt][nt][r] = 0.0f;

    const __nv_bfloat16* Abase_h = Ah + (size_t)m0 * K;
    const __nv_bfloat16* Abase_l = Al + (size_t)m0 * K;
    const __nv_bfloat16* Bbase_h = Bh + (size_t)n0 * K;
    const __nv_bfloat16* Bbase_l = Bl + (size_t)n0 * K;

    {
        u32 base = sb;
        load_tile_cp(Abase_h, K, base,                     tid);
        load_tile_cp(Abase_l, K, base + TG_TILE_BYTES,     tid);
        load_tile_cp(Bbase_h, K, base + 2 * TG_TILE_BYTES, tid);
        load_tile_cp(Bbase_l, K, base + 3 * TG_TILE_BYTES, tid);
        CP_COMMIT();
    }

    const int lrow = lane & 15;
    const int lcol = lane >> 4;

    for (int c = 0; c < NC; c++) {
        if (c + 1 < NC) {
            u32 base = sb + ((c + 1) & 1) * TG_STAGE_BYTES;
            const int kofs = (c + 1) * 32;
            load_tile_cp(Abase_h + kofs, K, base,                     tid);
            load_tile_cp(Abase_l + kofs, K, base + TG_TILE_BYTES,     tid);
            load_tile_cp(Bbase_h + kofs, K, base + 2 * TG_TILE_BYTES, tid);
            load_tile_cp(Bbase_l + kofs, K, base + 3 * TG_TILE_BYTES, tid);
            CP_COMMIT();
            CP_WAIT(1);
        } else {
            CP_WAIT(0);
        }
        __syncthreads();

        const u32 base = sb + (c & 1) * TG_STAGE_BYTES;
        const u32 sAh = base;
        const u32 sAl = base + TG_TILE_BYTES;
        const u32 sBh = base + 2 * TG_TILE_BYTES;
        const u32 sBl = base + 3 * TG_TILE_BYTES;

#pragma unroll
        for (int ks = 0; ks < 2; ks++) {
            u32 ah[4][4], al[4][4], bh[2][4], bl[2][4];
#pragma unroll
            for (int mt = 0; mt < 4; mt++) {
                int r  = wm * 64 + mt * 16 + lrow;
                int ch = 2 * ks + lcol;
                u32 off = r * 64 + 16 * (ch ^ ((r >> 1) & 3));
                LDSM_X4(ah[mt], sAh + off);
                LDSM_X4(al[mt], sAl + off);
            }
#pragma unroll
            for (int ng = 0; ng < 2; ng++) {
                int r  = wn * 32 + ng * 16 + lrow;
                int ch = 2 * ks + lcol;
                u32 off = r * 64 + 16 * (ch ^ ((r >> 1) & 3));
                LDSM_X4(bh[ng], sBh + off);
                LDSM_X4(bl[ng], sBl + off);
            }
#pragma unroll
            for (int mt = 0; mt < 4; mt++)
#pragma unroll
                for (int nt = 0; nt < 4; nt++) {
                    const int ng = nt >> 1, hi = nt & 1;
                    MMA_BF16(acc[mt][nt], ah[mt], bh[ng][hi], bh[ng][2 + hi]);
                    MMA_BF16(acc[mt][nt], ah[mt], bl[ng][hi], bl[ng][2 + hi]);
                    MMA_BF16(acc[mt][nt], al[mt], bh[ng][hi], bh[ng][2 + hi]);
                }
        }
        __syncthreads();
    }

    const int tg = lane >> 2;
    const int tc = (lane & 3) * 2;
#pragma unroll
    for (int mt = 0; mt < 4; mt++) {
#pragma unroll
        for (int half = 0; half < 2; half++) {
            const int m = m0 + wm * 64 + mt * 16 + tg + 8 * half;
#pragma unroll
            for (int nt = 0; nt < 4; nt++) {
                const int n = n0 + wn * 32 + nt * 8 + tc;
                float v0 = acc[mt][nt][2 * half]     + bias[n];
                float v1 = acc[mt][nt][2 * half + 1] + bias[n + 1];
                if (MODE == 0) {
                    *(float2*)(Cf + (size_t)m * N + n) = make_float2(v0, v1);
                } else {
                    if (MODE == 1) { v0 = fmaxf(v0, 0.0f); v1 = fmaxf(v1, 0.0f); }
                    else           { v0 *= scl; v1 *= scl; }
                    u32 hp, lp;
                    split2(v0, v1, hp, lp);
                    *(u32*)(Ch + (size_t)m * N + n) = hp;
                    *(u32*)(Cl + (size_t)m * N + n) = lp;
                }
            }
        }
    }
}

// ---------------------------------------------------------------------------
// HMMA flash attention with relative position bias (music-transformer skew).
//   logits[i,j] = Qs_i.K_j + Qs_i.rel[2047-(i-j)]   (Qs pre-scaled by 1/8)
// Q-tile 128 rows x key tiles of 64. 8 warps, each warp owns 16 rows x all 64
// keys. Split-bf16 3-pass HMMA for S, R, and PV. R (skew bias) kept as a
// 3-chunk rolling fp32 smem buffer; the diagonal gather is warp-local.
// CTA processes q-tiles (p, 15-p) -> uniform 34 key-tiles per CTA, 128 CTAs.
// ---------------------------------------------------------------------------
#define AT_STAGE 49152                 // 6 tiles x 8KB (kh,kl,fh,fl,vh,vl)
#define AT_R3OFF (2 * AT_STAGE)        // 98304
#define AT_RSTR  66                    // R3 row stride (floats)
#define AT_SLOT  (128 * AT_RSTR)       // floats per R3 slot
#define AT_SMEM  (AT_R3OFF + 3 * AT_SLOT * 4)   // 199680 bytes

__device__ __forceinline__ void attn_load_stage(
    u32 dstbase, int j0, int t, int tid, int b, int h,
    const __nv_bfloat16* __restrict__ kh, const __nv_bfloat16* __restrict__ kl,
    const __nv_bfloat16* __restrict__ relh, const __nv_bfloat16* __restrict__ rell,
    const __nv_bfloat16* __restrict__ vth, const __nv_bfloat16* __restrict__ vtl)
{
    const int r0 = tid >> 3, c = tid & 7;
#pragma unroll
    for (int i = 0; i < 2; i++) {
        const int r = r0 + 32 * i;
        const u32 sw = (u32)(r * 128 + 16 * (c ^ (r & 7)));
        const size_t krow = (size_t)(b * LL + j0 + r) * DD + h * DHH + 8 * c;
        const size_t frow = (size_t)(2047 - 64 * t - r) * DD + h * DHH + 8 * c;
        const size_t vrow = (size_t)((b * 8 + h) * 64 + r) * LL + j0 + 8 * c;
        cp16(dstbase +          sw, kh   + krow);
        cp16(dstbase +  8192 +  sw, kl   + krow);
        cp16(dstbase + 16384 +  sw, relh + frow);
        cp16(dstbase + 24576 +  sw, rell + frow);
        cp16(dstbase + 32768 +  sw, vth  + vrow);
        cp16(dstbase + 40960 +  sw, vtl  + vrow);
    }
}

__global__ __launch_bounds__(256, 1)
void attn_mma_kernel(const __nv_bfloat16* __restrict__ qh, const __nv_bfloat16* __restrict__ ql,
                     const __nv_bfloat16* __restrict__ kh, const __nv_bfloat16* __restrict__ kl,
                     const __nv_bfloat16* __restrict__ vth, const __nv_bfloat16* __restrict__ vtl,
                     const __nv_bfloat16* __restrict__ relh, const __nv_bfloat16* __restrict__ rell,
                     __nv_bfloat16* __restrict__ oh, __nv_bfloat16* __restrict__ ol)
{
    extern __shared__ char smem[];
    const u32 sb = smem_u32(smem);
    float* R3 = (float*)(smem + AT_R3OFF);

    const int tid = threadIdx.x, lane = tid & 31, w = tid >> 5;
    const int p   = blockIdx.x >> 4;
    const int bh  = blockIdx.x & 15;
    const int b   = bh >> 3, h = bh & 7;
    const int g   = lane >> 2, t4 = lane & 3;
    const int lr16 = lane & 15, lc = lane >> 4;

#pragma unroll 1
    for (int qq = 0; qq < 2; qq++) {
        const int q  = qq ? (15 - p) : p;
        const int i0 = q * 128;
        const int NT = 2 * q + 2;
        const int R0 = 16 * w + g, R1 = R0 + 8;
        const size_t rowg0 = (size_t)(b * LL + i0 + R0);

        // ---- Q fragments (A-operand, held in regs) ----
        u32 qfh[4][4], qfl[4][4];
        {
            const __nv_bfloat16* ph_ = qh + rowg0 * DD + h * DHH + 2 * t4;
            const __nv_bfloat16* pl_ = ql + rowg0 * DD + h * DHH + 2 * t4;
#pragma unroll
            for (int ks = 0; ks < 4; ks++) {
                qfh[ks][0] = *(const u32*)(ph_ + 16 * ks);
                qfh[ks][1] = *(const u32*)(ph_ + 16 * ks + 8 * DD);
                qfh[ks][2] = *(const u32*)(ph_ + 16 * ks + 8);
                qfh[ks][3] = *(const u32*)(ph_ + 16 * ks + 8 * DD + 8);
                qfl[ks][0] = *(const u32*)(pl_ + 16 * ks);
                qfl[ks][1] = *(const u32*)(pl_ + 16 * ks + 8 * DD);
                qfl[ks][2] = *(const u32*)(pl_ + 16 * ks + 8);
                qfl[ks][3] = *(const u32*)(pl_ + 16 * ks + 8 * DD + 8);
            }
        }

        float accO[8][4];
#pragma unroll
        for (int j = 0; j < 8; j++)
#pragma unroll
            for (int r = 0; r < 4; r++) accO[j][r] = 0.0f;
        float mrow0 = -1e30f, mrow1 = -1e30f, lrow0 = 0.0f, lrow1 = 0.0f;

        // prologue: tile 0 (j0 = i0+64, rel chunk 0)
        attn_load_stage(sb, i0 + 64, 0, tid, b, h, kh, kl, relh, rell, vth, vtl);
        CP_COMMIT();

#pragma unroll 1
        for (int t = 0; t < NT; t++) {
            const int j0 = i0 + 64 - 64 * t;
            if (t + 1 < NT) {
                attn_load_stage(sb + ((t + 1) & 1) * AT_STAGE, j0 - 64, t + 1,
                                tid, b, h, kh, kl, relh, rell, vth, vtl);
                CP_COMMIT();
                CP_WAIT(1);
            } else {
                CP_WAIT(0);
            }
            __syncthreads();

            const u32 st  = sb + (t & 1) * AT_STAGE;
            const u32 sKh = st, sKl = st + 8192, sFh = st + 16384,
                      sFl = st + 24576, sVh = st + 32768, sVl = st + 40960;

            // ---- R = Qs @ Fchunk^T -> smem slot t%3 ----
            {
                float racc[8][4];
#pragma unroll
                for (int j = 0; j < 8; j++)
#pragma unroll
                    for (int r = 0; r < 4; r++) racc[j][r] = 0.0f;
#pragma unroll
                for (int ks = 0; ks < 4; ks++) {
#pragma unroll
                    for (int ng = 0; ng < 4; ng++) {
                        const int row = 16 * ng + lr16;
                        const u32 off = (u32)(row * 128 + 16 * ((2 * ks + lc) ^ (row & 7)));
                        u32 bfh_[4], bfl_[4];
                        LDSM_X4(bfh_, sFh + off);
                        LDSM_X4(bfl_, sFl + off);
                        MMA_BF16(racc[2*ng],   qfh[ks], bfh_[0], bfh_[2]);
                        MMA_BF16(racc[2*ng+1], qfh[ks], bfh_[1], bfh_[3]);
                        MMA_BF16(racc[2*ng],   qfh[ks], bfl_[0], bfl_[2]);
                        MMA_BF16(racc[2*ng+1], qfh[ks], bfl_[1], bfl_[3]);
                        MMA_BF16(racc[2*ng],   qfl[ks], bfh_[0], bfh_[2]);
                        MMA_BF16(racc[2*ng+1], qfl[ks], bfh_[1], bfh_[3]);
                    }
                }
                float* Rb = R3 + (t % 3) * AT_SLOT;
#pragma unroll
                for (int j = 0; j < 8; j++) {
                    *(float2*)&Rb[R0 * AT_RSTR + 8 * j + 2 * t4] = make_float2(racc[j][0], racc[j][1]);
                    *(float2*)&Rb[R1 * AT_RSTR + 8 * j + 2 * t4] = make_float2(racc[j][2], racc[j][3]);
                }
            }
            __syncwarp();

            // ---- S = Qs @ K^T ----
            float sacc[8][4];
#pragma unroll
            for (int j = 0; j < 8; j++)
#pragma unroll
                for (int r = 0; r < 4; r++) sacc[j][r] = 0.0f;
#pragma unroll
            for (int ks = 0; ks < 4; ks++) {
#pragma unroll
                for (int ng = 0; ng < 4; ng++) {
                    const int row = 16 * ng + lr16;
                    const u32 off = (u32)(row * 128 + 16 * ((2 * ks + lc) ^ (row & 7)));
                    u32 bkh_[4], bkl_[4];
                    LDSM_X4(bkh_, sKh + off);
                    LDSM_X4(bkl_, sKl + off);
                    MMA_BF16(sacc[2*ng],   qfh[ks], bkh_[0], bkh_[2]);
                    MMA_BF16(sacc[2*ng+1], qfh[ks], bkh_[1], bkh_[3]);
                    MMA_BF16(sacc[2*ng],   qfh[ks], bkl_[0], bkl_[2]);
                    MMA_BF16(sacc[2*ng+1], qfh[ks], bkl_[1], bkl_[3]);
                    MMA_BF16(sacc[2*ng],   qfl[ks], bkh_[0], bkh_[2]);
                    MMA_BF16(sacc[2*ng+1], qfl[ks], bkh_[1], bkh_[3]);
                }
            }

            // ---- gather skew bias + mask + online softmax ----
            float mx0 = -1e30f, mx1 = -1e30f;
#pragma unroll
            for (int j = 0; j < 8; j++) {
#pragma unroll
                for (int c2 = 0; c2 < 2; c2++) {
                    const int dj = 8 * j + 2 * t4 + c2;
                    {
                        const int e = 64 + R0 - dj;
                        const int slot = (t + 1 + (e >> 6)) % 3;
                        float sv = sacc[j][c2] + R3[slot * AT_SLOT + R0 * AT_RSTR + (e & 63)];
                        if (t < 2 && (64 * (t - 1) + R0 - dj) < 0) sv = -1e30f;
                        sacc[j][c2] = sv;
                        mx0 = fmaxf(mx0, sv);
                    }
                    {
                        const int e = 64 + R1 - dj;
                        const int slot = (t + 1 + (e >> 6)) % 3;
                        float sv = sacc[j][2 + c2] + R3[slot * AT_SLOT + R1 * AT_RSTR + (e & 63)];
                        if (t < 2 && (64 * (t - 1) + R1 - dj) < 0) sv = -1e30f;
                        sacc[j][2 + c2] = sv;
                        mx1 = fmaxf(mx1, sv);
                    }
                }
            }
            mx0 = fmaxf(mx0, __shfl_xor_sync(0xffffffffu, mx0, 1));
            mx0 = fmaxf(mx0, __shfl_xor_sync(0xffffffffu, mx0, 2));
            mx1 = fmaxf(mx1, __shfl_xor_sync(0xffffffffu, mx1, 1));
            mx1 = fmaxf(mx1, __shfl_xor_sync(0xffffffffu, mx1, 2));

            const float mn0 = fmaxf(mrow0, mx0), mn1 = fmaxf(mrow1, mx1);
            const float al0 = __expf(mrow0 - mn0), al1 = __expf(mrow1 - mn1);
            mrow0 = mn0; mrow1 = mn1;

            float rs0 = 0.0f, rs1 = 0.0f;
#pragma unroll
            for (int j = 0; j < 8; j++) {
#pragma unroll
                for (int c2 = 0; c2 < 2; c2++) {
                    float sv = sacc[j][c2];
                    float e  = __expf(sv - mn0);
                    if (sv < -1e29f) e = 0.0f;
                    rs0 += e; sacc[j][c2] = e;
                    sv = sacc[j][2 + c2];
                    e  = __expf(sv - mn1);
                    if (sv < -1e29f) e = 0.0f;
                    rs1 += e; sacc[j][2 + c2] = e;
                }
            }
            rs0 += __shfl_xor_sync(0xffffffffu, rs0, 1);
            rs0 += __shfl_xor_sync(0xffffffffu, rs0, 2);
            rs1 += __shfl_xor_sync(0xffffffffu, rs1, 1);
            rs1 += __shfl_xor_sync(0xffffffffu, rs1, 2);
            lrow0 = lrow0 * al0 + rs0;
            lrow1 = lrow1 * al1 + rs1;
#pragma unroll
            for (int j = 0; j < 8; j++) {
                accO[j][0] *= al0; accO[j][1] *= al0;
                accO[j][2] *= al1; accO[j][3] *= al1;
            }

            // ---- O += P @ V (P repacked C-frag -> A-frag, split) ----
#pragma unroll
            for (int ks = 0; ks < 4; ks++) {
                u32 ph_[4], pl_[4];
                split2(sacc[2*ks][0],   sacc[2*ks][1],   ph_[0], pl_[0]);
                split2(sacc[2*ks][2],   sacc[2*ks][3],   ph_[1], pl_[1]);
                split2(sacc[2*ks+1][0], sacc[2*ks+1][1], ph_[2], pl_[2]);
                split2(sacc[2*ks+1][2], sacc[2*ks+1][3], ph_[3], pl_[3]);
#pragma unroll
                for (int ng = 0; ng < 4; ng++) {
                    const int row = 16 * ng + lr16;
                    const u32 off = (u32)(row * 128 + 16 * ((2 * ks + lc) ^ (row & 7)));
                    u32 bvh_[4], bvl_[4];
                    LDSM_X4(bvh_, sVh + off);
                    LDSM_X4(bvl_, sVl + off);
                    MMA_BF16(accO[2*ng],   ph_, bvh_[0], bvh_[2]);
                    MMA_BF16(accO[2*ng+1], ph_, bvh_[1], bvh_[3]);
                    MMA_BF16(accO[2*ng],   ph_, bvl_[0], bvl_[2]);
                    MMA_BF16(accO[2*ng+1], ph_, bvl_[1], bvl_[3]);
                    MMA_BF16(accO[2*ng],   pl_, bvh_[0], bvh_[2]);
                    MMA_BF16(accO[2*ng+1], pl_, bvh_[1], bvh_[3]);
                }
            }
            __syncthreads();
        }

        // ---- epilogue: normalize, split, store ----
        const float inv0 = 1.0f / lrow0, inv1 = 1.0f / lrow1;
        __nv_bfloat16* o0h = oh + rowg0 * DD + h * DHH + 2 * t4;
        __nv_bfloat16* o0l = ol + rowg0 * DD + h * DHH + 2 * t4;
#pragma unroll
        for (int j = 0; j < 8; j++) {
            u32 hp, lp;
            split2(accO[j][0] * inv0, accO[j][1] * inv0, hp, lp);
            *(u32*)(o0h + 8 * j) = hp;
            *(u32*)(o0l + 8 * j) = lp;
            split2(accO[j][2] * inv1, accO[j][3] * inv1, hp, lp);
            *(u32*)(o0h + 8 * DD + 8 * j) = hp;
            *(u32*)(o0l + 8 * DD + 8 * j) = lp;
        }
    }
}

// ---------------------------------------------------------------------------
// Launch
// ---------------------------------------------------------------------------
extern "C" void kernel_launch(void* const* d_in, const int* in_sizes, int n_in,
                              void* d_out, int out_size)
{
    const float* x   = (const float*)d_in[0];
    // d_in[1] = mask — handled analytically
    const float* wq  = (const float*)d_in[2];
    const float* bq  = (const float*)d_in[3];
    const float* wk  = (const float*)d_in[4];
    const float* bk  = (const float*)d_in[5];
    const float* wv  = (const float*)d_in[6];
    const float* bv  = (const float*)d_in[7];
    const float* rel = (const float*)d_in[8];
    const float* w1  = (const float*)d_in[9];
    const float* b1  = (const float*)d_in[10];
    const float* w2  = (const float*)d_in[11];
    const float* b2  = (const float*)d_in[12];
    float* out = (float*)d_out;

    float* Vp;
    __nv_bfloat16 *xh, *xl, *qh, *ql, *kh, *kl, *vth, *vtl, *relh, *rell;
    __nv_bfloat16 *ah, *al, *hhp, *hlp;
    __nv_bfloat16 *wqh, *wql, *wkh, *wkl, *wvh, *wvl, *w1h, *w1l, *w2h, *w2l;
    cudaGetSymbolAddress((void**)&Vp,  g_V);
    cudaGetSymbolAddress((void**)&xh,  g_xh);   cudaGetSymbolAddress((void**)&xl,  g_xl);
    cudaGetSymbolAddress((void**)&qh,  g_qh);   cudaGetSymbolAddress((void**)&ql,  g_ql);
    cudaGetSymbolAddress((void**)&kh,  g_kh);   cudaGetSymbolAddress((void**)&kl,  g_kl);
    cudaGetSymbolAddress((void**)&vth, g_vth);  cudaGetSymbolAddress((void**)&vtl, g_vtl);
    cudaGetSymbolAddress((void**)&relh, g_relh); cudaGetSymbolAddress((void**)&rell, g_rell);
    cudaGetSymbolAddress((void**)&ah,  g_ah);   cudaGetSymbolAddress((void**)&al,  g_al);
    cudaGetSymbolAddress((void**)&hhp, g_hh);   cudaGetSymbolAddress((void**)&hlp, g_hl);
    cudaGetSymbolAddress((void**)&wqh, g_wqh);  cudaGetSymbolAddress((void**)&wql, g_wql);
    cudaGetSymbolAddress((void**)&wkh, g_wkh);  cudaGetSymbolAddress((void**)&wkl, g_wkl);
    cudaGetSymbolAddress((void**)&wvh, g_wvh);  cudaGetSymbolAddress((void**)&wvl, g_wvl);
    cudaGetSymbolAddress((void**)&w1h, g_w1h);  cudaGetSymbolAddress((void**)&w1l, g_w1l);
    cudaGetSymbolAddress((void**)&w2h, g_w2h);  cudaGetSymbolAddress((void**)&w2l, g_w2l);

    cudaFuncSetAttribute(tgemm_kernel<0>, cudaFuncAttributeMaxDynamicSharedMemorySize, TG_SMEM);
    cudaFuncSetAttribute(tgemm_kernel<1>, cudaFuncAttributeMaxDynamicSharedMemorySize, TG_SMEM);
    cudaFuncSetAttribute(tgemm_kernel<2>, cudaFuncAttributeMaxDynamicSharedMemorySize, TG_SMEM);
    cudaFuncSetAttribute(attn_mma_kernel, cudaFuncAttributeMaxDynamicSharedMemorySize, AT_SMEM);

    // 0) Input/weight preparation
    convert_split_kernel<<<(MM * DD / 4 + 255) / 256, 256>>>((const float4*)x, xh, xl, MM * DD / 4);
    convert_split_kernel<<<(LL * DD / 4 + 255) / 256, 256>>>((const float4*)rel, relh, rell, LL * DD / 4);
    transpose_split_kernel<<<dim3(DD / 32,   DD / 32),   256>>>(wq, wqh, wql, DD,   DD);
    transpose_split_kernel<<<dim3(DD / 32,   DD / 32),   256>>>(wk, wkh, wkl, DD,   DD);
    transpose_split_kernel<<<dim3(DD / 32,   DD / 32),   256>>>(wv, wvh, wvl, DD,   DD);
    transpose_split_kernel<<<dim3(DFCN / 32, DD / 32),   256>>>(w1, w1h, w1l, DD,   DFCN);
    transpose_split_kernel<<<dim3(DD / 32,   DFCN / 32), 256>>>(w2, w2h, w2l, DFCN, DD);

    // 1) QKV projections: Q scaled by 1/8 and split; K split; V fp32 -> transpose
    tgemm_kernel<2><<<dim3(DD / 128, MM / 128), 256, TG_SMEM>>>(
        xh, xl, wqh, wql, bq, nullptr, qh, ql, MM, DD, DD, 0.125f);
    tgemm_kernel<2><<<dim3(DD / 128, MM / 128), 256, TG_SMEM>>>(
        xh, xl, wkh, wkl, bk, nullptr, kh, kl, MM, DD, DD, 1.0f);
    tgemm_kernel<0><<<dim3(DD / 128, MM / 128), 256, TG_SMEM>>>(
        xh, xl, wvh, wvl, bv, Vp, nullptr, nullptr, MM, DD, DD, 1.0f);
    vt_split_kernel<<<dim3(DD / 32, MM / 32), 256>>>(Vp, vth, vtl);

    // 2) HMMA flash attention with relative bias (writes split output)
    attn_mma_kernel<<<128, 256, AT_SMEM>>>(qh, ql, kh, kl, vth, vtl, relh, rell, ah, al);

    // 3) FFN
    tgemm_kernel<1><<<dim3(DFCN / 128, MM / 128), 256, TG_SMEM>>>(
        ah, al, w1h, w1l, b1, nullptr, hhp, hlp, MM, DFCN, DD, 1.0f);
    tgemm_kernel<0><<<dim3(DD / 128, MM / 128), 256, TG_SMEM>>>(
        hhp, hlp, w2h, w2l, b2, out, nullptr, nullptr, MM, DD, DFCN, 1.0f);
}

// round 9
// speedup vs baseline: 2.8634x; 1.0834x over previous
#include <cuda_runtime.h>
#include <cuda_bf16.h>
#include <cstdint>
#include <cstddef>

// ---------------------------------------------------------------------------
// Problem constants
// ---------------------------------------------------------------------------
#define BB   2
#define LL   2048
#define DD   512
#define HH   8
#define DHH  64
#define DFCN 2048
#define MM   (BB * LL)        // 4096 rows

typedef unsigned long long u64;
typedef unsigned int u32;

// ---------------------------------------------------------------------------
// Scratch (device globals: allocation-guard-safe)
// ---------------------------------------------------------------------------
__device__ float g_V[MM * DD];                                // V fp32 (pre-transpose)

__device__ __nv_bfloat16 g_xh[MM * DD],   g_xl[MM * DD];      // split x
__device__ __nv_bfloat16 g_qh[MM * DD],   g_ql[MM * DD];      // split scaled Q
__device__ __nv_bfloat16 g_kh[MM * DD],   g_kl[MM * DD];      // split K
__device__ __nv_bfloat16 g_vth[BB*HH*DHH * LL], g_vtl[BB*HH*DHH * LL]; // V^T split
__device__ __nv_bfloat16 g_relh[LL * DD], g_rell[LL * DD];    // split rel_emb
__device__ __nv_bfloat16 g_ah[MM * DD],   g_al[MM * DD];      // split attn out
__device__ __nv_bfloat16 g_hh[MM * DFCN], g_hl[MM * DFCN];    // split FFN hidden

// Transposed + split weights: T[n][k] = W[k][n]
__device__ __nv_bfloat16 g_wqh[DD * DD],   g_wql[DD * DD];
__device__ __nv_bfloat16 g_wkh[DD * DD],   g_wkl[DD * DD];
__device__ __nv_bfloat16 g_wvh[DD * DD],   g_wvl[DD * DD];
__device__ __nv_bfloat16 g_w1h[DFCN * DD], g_w1l[DFCN * DD];
__device__ __nv_bfloat16 g_w2h[DD * DFCN], g_w2l[DD * DFCN];

// ---------------------------------------------------------------------------
// Helpers
// ---------------------------------------------------------------------------
__device__ __forceinline__ u32 smem_u32(const void* p) {
    u32 a;
    asm("{ .reg .u64 t; cvta.to.shared.u64 t, %1; cvt.u32.u64 %0, t; }"
        : "=r"(a) : "l"(p));
    return a;
}

__device__ __forceinline__ u32 pack_bf2(__nv_bfloat16 a, __nv_bfloat16 b) {
    return (u32)__bfloat16_as_ushort(a) | ((u32)__bfloat16_as_ushort(b) << 16);
}

__device__ __forceinline__ void split2(float x, float y, u32& hp, u32& lp) {
    __nv_bfloat16 hx = __float2bfloat16(x), hy = __float2bfloat16(y);
    hp = pack_bf2(hx, hy);
    lp = pack_bf2(__float2bfloat16(x - __bfloat162float(hx)),
                  __float2bfloat16(y - __bfloat162float(hy)));
}

#define LDSM_X4(r, addr) \
    asm volatile("ldmatrix.sync.aligned.m8n8.x4.shared.b16 {%0,%1,%2,%3}, [%4];" \
        : "=r"((r)[0]), "=r"((r)[1]), "=r"((r)[2]), "=r"((r)[3]) : "r"(addr))

#define MMA_BF16(d, a, b0, b1) \
    asm volatile("mma.sync.aligned.m16n8k16.row.col.f32.bf16.bf16.f32 " \
        "{%0,%1,%2,%3}, {%4,%5,%6,%7}, {%8,%9}, {%0,%1,%2,%3};" \
        : "+f"((d)[0]), "+f"((d)[1]), "+f"((d)[2]), "+f"((d)[3]) \
        : "r"((a)[0]), "r"((a)[1]), "r"((a)[2]), "r"((a)[3]), "r"(b0), "r"(b1))

__device__ __forceinline__ void cp16(u32 dst, const void* src) {
    asm volatile("cp.async.cg.shared.global [%0], [%1], 16;"
                 :: "r"(dst), "l"(src) : "memory");
}
#define CP_COMMIT()  asm volatile("cp.async.commit_group;" ::: "memory")
#define CP_WAIT(n)   asm volatile("cp.async.wait_group %0;" :: "n"(n) : "memory")

// ---------------------------------------------------------------------------
// Prep kernels
// ---------------------------------------------------------------------------
// 3 same-shape weight transposes in one launch (z selects matrix)
__global__ __launch_bounds__(256)
void tsplit3_kernel(const float* __restrict__ wq, const float* __restrict__ wk,
                    const float* __restrict__ wv,
                    __nv_bfloat16* __restrict__ qhh, __nv_bfloat16* __restrict__ qll,
                    __nv_bfloat16* __restrict__ khh, __nv_bfloat16* __restrict__ kll,
                    __nv_bfloat16* __restrict__ vhh, __nv_bfloat16* __restrict__ vll)
{
    const float* W = blockIdx.z == 0 ? wq : blockIdx.z == 1 ? wk : wv;
    __nv_bfloat16* Th = blockIdx.z == 0 ? qhh : blockIdx.z == 1 ? khh : vhh;
    __nv_bfloat16* Tl = blockIdx.z == 0 ? qll : blockIdx.z == 1 ? kll : vll;

    __shared__ float t[32][33];
    const int n0 = blockIdx.x * 32, k0 = blockIdx.y * 32;
    const int tx = threadIdx.x & 31, ty = threadIdx.x >> 5;
#pragma unroll
    for (int i = 0; i < 4; i++)
        t[ty + 8 * i][tx] = W[(size_t)(k0 + ty + 8 * i) * DD + n0 + tx];
    __syncthreads();
#pragma unroll
    for (int i = 0; i < 4; i++) {
        int n = n0 + ty + 8 * i;
        float v = t[tx][ty + 8 * i];
        __nv_bfloat16 h = __float2bfloat16(v);
        Th[(size_t)n * DD + k0 + tx] = h;
        Tl[(size_t)n * DD + k0 + tx] = __float2bfloat16(v - __bfloat162float(h));
    }
}

__global__ __launch_bounds__(256)
void transpose_split_kernel(const float* __restrict__ W,
                            __nv_bfloat16* __restrict__ Th,
                            __nv_bfloat16* __restrict__ Tl,
                            int K, int N)
{
    __shared__ float t[32][33];
    const int n0 = blockIdx.x * 32, k0 = blockIdx.y * 32;
    const int tx = threadIdx.x & 31, ty = threadIdx.x >> 5;
#pragma unroll
    for (int i = 0; i < 4; i++)
        t[ty + 8 * i][tx] = W[(size_t)(k0 + ty + 8 * i) * N + n0 + tx];
    __syncthreads();
#pragma unroll
    for (int i = 0; i < 4; i++) {
        int n = n0 + ty + 8 * i;
        float v = t[tx][ty + 8 * i];
        __nv_bfloat16 h = __float2bfloat16(v);
        Th[(size_t)n * K + k0 + tx] = h;
        Tl[(size_t)n * K + k0 + tx] = __float2bfloat16(v - __bfloat162float(h));
    }
}

// V transpose + split: g_V fp32 [B*L][512] -> Vt[b*512 + col][token in b] bf16
__global__ __launch_bounds__(256)
void vt_split_kernel(const float* __restrict__ V,
                     __nv_bfloat16* __restrict__ Th,
                     __nv_bfloat16* __restrict__ Tl)
{
    __shared__ float t[32][33];
    const int n0 = blockIdx.x * 32;
    const int k0 = blockIdx.y * 32;
    const int b  = k0 >> 11;
    const int tx = threadIdx.x & 31, ty = threadIdx.x >> 5;
#pragma unroll
    for (int i = 0; i < 4; i++)
        t[ty + 8 * i][tx] = V[(size_t)(k0 + ty + 8 * i) * DD + n0 + tx];
    __syncthreads();
#pragma unroll
    for (int i = 0; i < 4; i++) {
        int n = n0 + ty + 8 * i;
        float v = t[tx][ty + 8 * i];
        __nv_bfloat16 h = __float2bfloat16(v);
        size_t o = (size_t)(b * 512 + n) * LL + (k0 & 2047) + tx;
        Th[o] = h;
        Tl[o] = __float2bfloat16(v - __bfloat162float(h));
    }
}

// Fused elementwise split of x and rel_emb (one launch)
#define N4X (MM * DD / 4)
#define N4R (LL * DD / 4)
__global__ __launch_bounds__(256)
void conv_xrel_kernel(const float4* __restrict__ X, const float4* __restrict__ R,
                      __nv_bfloat16* __restrict__ XH, __nv_bfloat16* __restrict__ XL,
                      __nv_bfloat16* __restrict__ RH, __nv_bfloat16* __restrict__ RL)
{
    int i = blockIdx.x * blockDim.x + threadIdx.x;
    const float4* src; __nv_bfloat16 *H, *L; int j;
    if (i < N4X) { src = X; H = XH; L = XL; j = i; }
    else if (i < N4X + N4R) { src = R; H = RH; L = RL; j = i - N4X; }
    else return;
    float4 v = src[j];
    u32 h0, l0, h1, l1;
    split2(v.x, v.y, h0, l0);
    split2(v.z, v.w, h1, l1);
    *(uint2*)(H + 4 * (size_t)j) = make_uint2(h0, h1);
    *(uint2*)(L + 4 * (size_t)j) = make_uint2(l0, l1);
}

// ---------------------------------------------------------------------------
// Split-bf16 HMMA GEMM core: BK=64, 3-stage cp.async ring, 128x128 CTA tile,
// 8 warps (2x4), 64x32 warp tile. Smem rows are 128B (64 bf16), XOR-8 swizzle.
// ---------------------------------------------------------------------------
#define TGX_TILE  16384                 // 128 x 64 x 2B
#define TGX_STAGE (4 * TGX_TILE)        // Ah, Al, Bh, Bl = 64KB
#define TGX_SMEM  (3 * TGX_STAGE)       // 192KB

__device__ __forceinline__ void load_tile64(const __nv_bfloat16* __restrict__ src,
                                            int ldk, u32 sdst, int tid)
{
    // 128 rows x 8 16B chunks = 1024 chunks, 256 threads x 4
#pragma unroll
    for (int i = 0; i < 4; i++) {
        int idx = tid + 256 * i;
        int r = idx >> 3, c = idx & 7;
        cp16(sdst + r * 128 + 16 * (c ^ (r & 7)), src + (size_t)r * ldk + 8 * c);
    }
}

__device__ __forceinline__ void tgx_stage_load(
    u32 sdst, const __nv_bfloat16* Ah, const __nv_bfloat16* Al,
    const __nv_bfloat16* Bh, const __nv_bfloat16* Bl, int K, int kofs, int tid)
{
    load_tile64(Ah + kofs, K, sdst,                tid);
    load_tile64(Al + kofs, K, sdst +     TGX_TILE, tid);
    load_tile64(Bh + kofs, K, sdst + 2 * TGX_TILE, tid);
    load_tile64(Bl + kofs, K, sdst + 3 * TGX_TILE, tid);
}

// computes acc (4x4 tiles of m16n8) for one 64-wide chunk
__device__ __forceinline__ void tgx_compute_chunk(
    u32 base, int wm, int wn, int lr16, int lc, float acc[4][4][4])
{
    const u32 sAh = base, sAl = base + TGX_TILE,
              sBh = base + 2 * TGX_TILE, sBl = base + 3 * TGX_TILE;
#pragma unroll
    for (int ks = 0; ks < 4; ks++) {
        u32 ah[4][4], al[4][4], bh[2][4], bl[2][4];
#pragma unroll
        for (int mt = 0; mt < 4; mt++) {
            int r  = wm * 64 + mt * 16 + lr16;
            int ch = 2 * ks + lc;
            u32 off = r * 128 + 16 * (ch ^ (r & 7));
            LDSM_X4(ah[mt], sAh + off);
            LDSM_X4(al[mt], sAl + off);
        }
#pragma unroll
        for (int ng = 0; ng < 2; ng++) {
            int r  = wn * 32 + ng * 16 + lr16;
            int ch = 2 * ks + lc;
            u32 off = r * 128 + 16 * (ch ^ (r & 7));
            LDSM_X4(bh[ng], sBh + off);
            LDSM_X4(bl[ng], sBl + off);
        }
#pragma unroll
        for (int mt = 0; mt < 4; mt++)
#pragma unroll
            for (int nt = 0; nt < 4; nt++) {
                const int ng = nt >> 1, hi = nt & 1;
                MMA_BF16(acc[mt][nt], ah[mt], bh[ng][hi], bh[ng][2 + hi]);
                MMA_BF16(acc[mt][nt], ah[mt], bl[ng][hi], bl[ng][2 + hi]);
                MMA_BF16(acc[mt][nt], al[mt], bh[ng][hi], bh[ng][2 + hi]);
            }
    }
}

// Full 3-stage mainloop producing acc
__device__ __forceinline__ void tgx_mainloop(
    u32 sb, const __nv_bfloat16* Abase_h, const __nv_bfloat16* Abase_l,
    const __nv_bfloat16* Bbase_h, const __nv_bfloat16* Bbase_l,
    int K, int tid, int wm, int wn, int lr16, int lc, float acc[4][4][4])
{
    const int NC = K >> 6;
    tgx_stage_load(sb, Abase_h, Abase_l, Bbase_h, Bbase_l, K, 0, tid);
    CP_COMMIT();
    if (NC > 1) {
        tgx_stage_load(sb + TGX_STAGE, Abase_h, Abase_l, Bbase_h, Bbase_l, K, 64, tid);
        CP_COMMIT();
    }
    for (int c = 0; c < NC; c++) {
        CP_WAIT(1);
        __syncthreads();
        if (c + 2 < NC) {
            tgx_stage_load(sb + ((c + 2) % 3) * TGX_STAGE,
                           Abase_h, Abase_l, Bbase_h, Bbase_l, K, (c + 2) * 64, tid);
            CP_COMMIT();
        } else {
            CP_COMMIT();  // keep group count in sync for CP_WAIT(1)
        }
        tgx_compute_chunk(sb + (c % 3) * TGX_STAGE, wm, wn, lr16, lc, acc);
    }
}

// Generic GEMM: MODE 0 fp32 out, MODE 1 relu+split, MODE 2 scale+split
template <int MODE>
__global__ __launch_bounds__(256, 1)
void tgemm_kernel(const __nv_bfloat16* __restrict__ Ah,
                  const __nv_bfloat16* __restrict__ Al,
                  const __nv_bfloat16* __restrict__ Bh,
                  const __nv_bfloat16* __restrict__ Bl,
                  const float* __restrict__ bias,
                  float* __restrict__ Cf,
                  __nv_bfloat16* __restrict__ Ch,
                  __nv_bfloat16* __restrict__ Cl,
                  int M, int N, int K, float scl)
{
    extern __shared__ char smem[];
    const u32 sb = smem_u32(smem);
    const int tid  = threadIdx.x;
    const int wid  = tid >> 5, lane = tid & 31;
    const int wm   = wid >> 2, wn = wid & 3;
    const int m0   = blockIdx.y * 128;
    const int n0   = blockIdx.x * 128;
    const int lr16 = lane & 15, lc = lane >> 4;

    float acc[4][4][4];
#pragma unroll
    for (int mt = 0; mt < 4; mt++)
#pragma unroll
        for (int nt = 0; nt < 4; nt++)
#pragma unroll
            for (int r = 0; r < 4; r++) acc[mt][nt][r] = 0.0f;

    tgx_mainloop(sb, Ah + (size_t)m0 * K, Al + (size_t)m0 * K,
                 Bh + (size_t)n0 * K, Bl + (size_t)n0 * K,
                 K, tid, wm, wn, lr16, lc, acc);

    const int tg = lane >> 2;
    const int tc = (lane & 3) * 2;
#pragma unroll
    for (int mt = 0; mt < 4; mt++) {
#pragma unroll
        for (int half = 0; half < 2; half++) {
            const int m = m0 + wm * 64 + mt * 16 + tg + 8 * half;
#pragma unroll
            for (int nt = 0; nt < 4; nt++) {
                const int n = n0 + wn * 32 + nt * 8 + tc;
                float v0 = acc[mt][nt][2 * half]     + bias[n];
                float v1 = acc[mt][nt][2 * half + 1] + bias[n + 1];
                if (MODE == 0) {
                    *(float2*)(Cf + (size_t)m * N + n) = make_float2(v0, v1);
                } else {
                    if (MODE == 1) { v0 = fmaxf(v0, 0.0f); v1 = fmaxf(v1, 0.0f); }
                    else           { v0 *= scl; v1 *= scl; }
                    u32 hp, lp;
                    split2(v0, v1, hp, lp);
                    *(u32*)(Ch + (size_t)m * N + n) = hp;
                    *(u32*)(Cl + (size_t)m * N + n) = lp;
                }
            }
        }
    }
}

// Fused QKV: blockIdx.z selects weight/bias/output.
// z=0: Q (scale 1/8, split out). z=1: K (split out). z=2: V (fp32 out).
__global__ __launch_bounds__(256, 1)
void qkv_fused_kernel(const __nv_bfloat16* __restrict__ xh,
                      const __nv_bfloat16* __restrict__ xl,
                      const __nv_bfloat16* __restrict__ wqh, const __nv_bfloat16* __restrict__ wql,
                      const __nv_bfloat16* __restrict__ wkh, const __nv_bfloat16* __restrict__ wkl,
                      const __nv_bfloat16* __restrict__ wvh, const __nv_bfloat16* __restrict__ wvl,
                      const float* __restrict__ bq, const float* __restrict__ bk,
                      const float* __restrict__ bv,
                      __nv_bfloat16* __restrict__ qh, __nv_bfloat16* __restrict__ ql,
                      __nv_bfloat16* __restrict__ kh, __nv_bfloat16* __restrict__ kl,
                      float* __restrict__ Vf)
{
    extern __shared__ char smem[];
    const u32 sb = smem_u32(smem);
    const int tid  = threadIdx.x;
    const int wid  = tid >> 5, lane = tid & 31;
    const int wm   = wid >> 2, wn = wid & 3;
    const int m0   = blockIdx.y * 128;
    const int n0   = blockIdx.x * 128;
    const int z    = blockIdx.z;
    const int lr16 = lane & 15, lc = lane >> 4;

    const __nv_bfloat16* Bh = z == 0 ? wqh : z == 1 ? wkh : wvh;
    const __nv_bfloat16* Bl = z == 0 ? wql : z == 1 ? wkl : wvl;
    const float* bias       = z == 0 ? bq  : z == 1 ? bk  : bv;

    float acc[4][4][4];
#pragma unroll
    for (int mt = 0; mt < 4; mt++)
#pragma unroll
        for (int nt = 0; nt < 4; nt++)
#pragma unroll
            for (int r = 0; r < 4; r++) acc[mt][nt][r] = 0.0f;

    tgx_mainloop(sb, xh + (size_t)m0 * DD, xl + (size_t)m0 * DD,
                 Bh + (size_t)n0 * DD, Bl + (size_t)n0 * DD,
                 DD, tid, wm, wn, lr16, lc, acc);

    const int tg = lane >> 2;
    const int tc = (lane & 3) * 2;
    const float scl = (z == 0) ? 0.125f : 1.0f;
    __nv_bfloat16* Ch = z == 0 ? qh : kh;
    __nv_bfloat16* Cl = z == 0 ? ql : kl;
#pragma unroll
    for (int mt = 0; mt < 4; mt++) {
#pragma unroll
        for (int half = 0; half < 2; half++) {
            const int m = m0 + wm * 64 + mt * 16 + tg + 8 * half;
#pragma unroll
            for (int nt = 0; nt < 4; nt++) {
                const int n = n0 + wn * 32 + nt * 8 + tc;
                float v0 = acc[mt][nt][2 * half]     + bias[n];
                float v1 = acc[mt][nt][2 * half + 1] + bias[n + 1];
                if (z == 2) {
                    *(float2*)(Vf + (size_t)m * DD + n) = make_float2(v0, v1);
                } else {
                    v0 *= scl; v1 *= scl;
                    u32 hp, lp;
                    split2(v0, v1, hp, lp);
                    *(u32*)(Ch + (size_t)m * DD + n) = hp;
                    *(u32*)(Cl + (size_t)m * DD + n) = lp;
                }
            }
        }
    }
}

// ---------------------------------------------------------------------------
// HMMA flash attention with relative position bias (unchanged from round 7).
// ---------------------------------------------------------------------------
#define AT_STAGE 49152
#define AT_R3OFF (2 * AT_STAGE)
#define AT_RSTR  66
#define AT_SLOT  (128 * AT_RSTR)
#define AT_SMEM  (AT_R3OFF + 3 * AT_SLOT * 4)

__device__ __forceinline__ void attn_load_stage(
    u32 dstbase, int j0, int t, int tid, int b, int h,
    const __nv_bfloat16* __restrict__ kh, const __nv_bfloat16* __restrict__ kl,
    const __nv_bfloat16* __restrict__ relh, const __nv_bfloat16* __restrict__ rell,
    const __nv_bfloat16* __restrict__ vth, const __nv_bfloat16* __restrict__ vtl)
{
    const int r0 = tid >> 3, c = tid & 7;
#pragma unroll
    for (int i = 0; i < 2; i++) {
        const int r = r0 + 32 * i;
        const u32 sw = (u32)(r * 128 + 16 * (c ^ (r & 7)));
        const size_t krow = (size_t)(b * LL + j0 + r) * DD + h * DHH + 8 * c;
        const size_t frow = (size_t)(2047 - 64 * t - r) * DD + h * DHH + 8 * c;
        const size_t vrow = (size_t)((b * 8 + h) * 64 + r) * LL + j0 + 8 * c;
        cp16(dstbase +          sw, kh   + krow);
        cp16(dstbase +  8192 +  sw, kl   + krow);
        cp16(dstbase + 16384 +  sw, relh + frow);
        cp16(dstbase + 24576 +  sw, rell + frow);
        cp16(dstbase + 32768 +  sw, vth  + vrow);
        cp16(dstbase + 40960 +  sw, vtl  + vrow);
    }
}

__global__ __launch_bounds__(256, 1)
void attn_mma_kernel(const __nv_bfloat16* __restrict__ qh, const __nv_bfloat16* __restrict__ ql,
                     const __nv_bfloat16* __restrict__ kh, const __nv_bfloat16* __restrict__ kl,
                     const __nv_bfloat16* __restrict__ vth, const __nv_bfloat16* __restrict__ vtl,
                     const __nv_bfloat16* __restrict__ relh, const __nv_bfloat16* __restrict__ rell,
                     __nv_bfloat16* __restrict__ oh, __nv_bfloat16* __restrict__ ol)
{
    extern __shared__ char smem[];
    const u32 sb = smem_u32(smem);
    float* R3 = (float*)(smem + AT_R3OFF);

    const int tid = threadIdx.x, lane = tid & 31, w = tid >> 5;
    const int p   = blockIdx.x >> 4;
    const int bh  = blockIdx.x & 15;
    const int b   = bh >> 3, h = bh & 7;
    const int g   = lane >> 2, t4 = lane & 3;
    const int lr16 = lane & 15, lc = lane >> 4;

#pragma unroll 1
    for (int qq = 0; qq < 2; qq++) {
        const int q  = qq ? (15 - p) : p;
        const int i0 = q * 128;
        const int NT = 2 * q + 2;
        const int R0 = 16 * w + g, R1 = R0 + 8;
        const size_t rowg0 = (size_t)(b * LL + i0 + R0);

        u32 qfh[4][4], qfl[4][4];
        {
            const __nv_bfloat16* ph_ = qh + rowg0 * DD + h * DHH + 2 * t4;
            const __nv_bfloat16* pl_ = ql + rowg0 * DD + h * DHH + 2 * t4;
#pragma unroll
            for (int ks = 0; ks < 4; ks++) {
                qfh[ks][0] = *(const u32*)(ph_ + 16 * ks);
                qfh[ks][1] = *(const u32*)(ph_ + 16 * ks + 8 * DD);
                qfh[ks][2] = *(const u32*)(ph_ + 16 * ks + 8);
                qfh[ks][3] = *(const u32*)(ph_ + 16 * ks + 8 * DD + 8);
                qfl[ks][0] = *(const u32*)(pl_ + 16 * ks);
                qfl[ks][1] = *(const u32*)(pl_ + 16 * ks + 8 * DD);
                qfl[ks][2] = *(const u32*)(pl_ + 16 * ks + 8);
                qfl[ks][3] = *(const u32*)(pl_ + 16 * ks + 8 * DD + 8);
            }
        }

        float accO[8][4];
#pragma unroll
        for (int j = 0; j < 8; j++)
#pragma unroll
            for (int r = 0; r < 4; r++) accO[j][r] = 0.0f;
        float mrow0 = -1e30f, mrow1 = -1e30f, lrow0 = 0.0f, lrow1 = 0.0f;

        attn_load_stage(sb, i0 + 64, 0, tid, b, h, kh, kl, relh, rell, vth, vtl);
        CP_COMMIT();

#pragma unroll 1
        for (int t = 0; t < NT; t++) {
            const int j0 = i0 + 64 - 64 * t;
            if (t + 1 < NT) {
                attn_load_stage(sb + ((t + 1) & 1) * AT_STAGE, j0 - 64, t + 1,
                                tid, b, h, kh, kl, relh, rell, vth, vtl);
                CP_COMMIT();
                CP_WAIT(1);
            } else {
                CP_WAIT(0);
            }
            __syncthreads();

            const u32 st  = sb + (t & 1) * AT_STAGE;
            const u32 sKh = st, sKl = st + 8192, sFh = st + 16384,
                      sFl = st + 24576, sVh = st + 32768, sVl = st + 40960;

            // R = Qs @ Fchunk^T
            {
                float racc[8][4];
#pragma unroll
                for (int j = 0; j < 8; j++)
#pragma unroll
                    for (int r = 0; r < 4; r++) racc[j][r] = 0.0f;
#pragma unroll
                for (int ks = 0; ks < 4; ks++) {
#pragma unroll
                    for (int ng = 0; ng < 4; ng++) {
                        const int row = 16 * ng + lr16;
                        const u32 off = (u32)(row * 128 + 16 * ((2 * ks + lc) ^ (row & 7)));
                        u32 bfh_[4], bfl_[4];
                        LDSM_X4(bfh_, sFh + off);
                        LDSM_X4(bfl_, sFl + off);
                        MMA_BF16(racc[2*ng],   qfh[ks], bfh_[0], bfh_[2]);
                        MMA_BF16(racc[2*ng+1], qfh[ks], bfh_[1], bfh_[3]);
                        MMA_BF16(racc[2*ng],   qfh[ks], bfl_[0], bfl_[2]);
                        MMA_BF16(racc[2*ng+1], qfh[ks], bfl_[1], bfl_[3]);
                        MMA_BF16(racc[2*ng],   qfl[ks], bfh_[0], bfh_[2]);
                        MMA_BF16(racc[2*ng+1], qfl[ks], bfh_[1], bfh_[3]);
                    }
                }
                float* Rb = R3 + (t % 3) * AT_SLOT;
#pragma unroll
                for (int j = 0; j < 8; j++) {
                    *(float2*)&Rb[R0 * AT_RSTR + 8 * j + 2 * t4] = make_float2(racc[j][0], racc[j][1]);
                    *(float2*)&Rb[R1 * AT_RSTR + 8 * j + 2 * t4] = make_float2(racc[j][2], racc[j][3]);
                }
            }
            __syncwarp();

            // S = Qs @ K^T
            float sacc[8][4];
#pragma unroll
            for (int j = 0; j < 8; j++)
#pragma unroll
                for (int r = 0; r < 4; r++) sacc[j][r] = 0.0f;
#pragma unroll
            for (int ks = 0; ks < 4; ks++) {
#pragma unroll
                for (int ng = 0; ng < 4; ng++) {
                    const int row = 16 * ng + lr16;
                    const u32 off = (u32)(row * 128 + 16 * ((2 * ks + lc) ^ (row & 7)));
                    u32 bkh_[4], bkl_[4];
                    LDSM_X4(bkh_, sKh + off);
                    LDSM_X4(bkl_, sKl + off);
                    MMA_BF16(sacc[2*ng],   qfh[ks], bkh_[0], bkh_[2]);
                    MMA_BF16(sacc[2*ng+1], qfh[ks], bkh_[1], bkh_[3]);
                    MMA_BF16(sacc[2*ng],   qfh[ks], bkl_[0], bkl_[2]);
                    MMA_BF16(sacc[2*ng+1], qfh[ks], bkl_[1], bkl_[3]);
                    MMA_BF16(sacc[2*ng],   qfl[ks], bkh_[0], bkh_[2]);
                    MMA_BF16(sacc[2*ng+1], qfl[ks], bkh_[1], bkh_[3]);
                }
            }

            // gather skew bias + mask + online softmax
            float mx0 = -1e30f, mx1 = -1e30f;
#pragma unroll
            for (int j = 0; j < 8; j++) {
#pragma unroll
                for (int c2 = 0; c2 < 2; c2++) {
                    const int dj = 8 * j + 2 * t4 + c2;
                    {
                        const int e = 64 + R0 - dj;
                        const int slot = (t + 1 + (e >> 6)) % 3;
                        float sv = sacc[j][c2] + R3[slot * AT_SLOT + R0 * AT_RSTR + (e & 63)];
                        if (t < 2 && (64 * (t - 1) + R0 - dj) < 0) sv = -1e30f;
                        sacc[j][c2] = sv;
                        mx0 = fmaxf(mx0, sv);
                    }
                    {
                        const int e = 64 + R1 - dj;
                        const int slot = (t + 1 + (e >> 6)) % 3;
                        float sv = sacc[j][2 + c2] + R3[slot * AT_SLOT + R1 * AT_RSTR + (e & 63)];
                        if (t < 2 && (64 * (t - 1) + R1 - dj) < 0) sv = -1e30f;
                        sacc[j][2 + c2] = sv;
                        mx1 = fmaxf(mx1, sv);
                    }
                }
            }
            mx0 = fmaxf(mx0, __shfl_xor_sync(0xffffffffu, mx0, 1));
            mx0 = fmaxf(mx0, __shfl_xor_sync(0xffffffffu, mx0, 2));
            mx1 = fmaxf(mx1, __shfl_xor_sync(0xffffffffu, mx1, 1));
            mx1 = fmaxf(mx1, __shfl_xor_sync(0xffffffffu, mx1, 2));

            const float mn0 = fmaxf(mrow0, mx0), mn1 = fmaxf(mrow1, mx1);
            const float al0 = __expf(mrow0 - mn0), al1 = __expf(mrow1 - mn1);
            mrow0 = mn0; mrow1 = mn1;

            float rs0 = 0.0f, rs1 = 0.0f;
#pragma unroll
            for (int j = 0; j < 8; j++) {
#pragma unroll
                for (int c2 = 0; c2 < 2; c2++) {
                    float sv = sacc[j][c2];
                    float e  = __expf(sv - mn0);
                    if (sv < -1e29f) e = 0.0f;
                    rs0 += e; sacc[j][c2] = e;
                    sv = sacc[j][2 + c2];
                    e  = __expf(sv - mn1);
                    if (sv < -1e29f) e = 0.0f;
                    rs1 += e; sacc[j][2 + c2] = e;
                }
            }
            rs0 += __shfl_xor_sync(0xffffffffu, rs0, 1);
            rs0 += __shfl_xor_sync(0xffffffffu, rs0, 2);
            rs1 += __shfl_xor_sync(0xffffffffu, rs1, 1);
            rs1 += __shfl_xor_sync(0xffffffffu, rs1, 2);
            lrow0 = lrow0 * al0 + rs0;
            lrow1 = lrow1 * al1 + rs1;
#pragma unroll
            for (int j = 0; j < 8; j++) {
                accO[j][0] *= al0; accO[j][1] *= al0;
                accO[j][2] *= al1; accO[j][3] *= al1;
            }

            // O += P @ V
#pragma unroll
            for (int ks = 0; ks < 4; ks++) {
                u32 ph_[4], pl_[4];
                split2(sacc[2*ks][0],   sacc[2*ks][1],   ph_[0], pl_[0]);
                split2(sacc[2*ks][2],   sacc[2*ks][3],   ph_[1], pl_[1]);
                split2(sacc[2*ks+1][0], sacc[2*ks+1][1], ph_[2], pl_[2]);
                split2(sacc[2*ks+1][2], sacc[2*ks+1][3], ph_[3], pl_[3]);
#pragma unroll
                for (int ng = 0; ng < 4; ng++) {
                    const int row = 16 * ng + lr16;
                    const u32 off = (u32)(row * 128 + 16 * ((2 * ks + lc) ^ (row & 7)));
                    u32 bvh_[4], bvl_[4];
                    LDSM_X4(bvh_, sVh + off);
                    LDSM_X4(bvl_, sVl + off);
                    MMA_BF16(accO[2*ng],   ph_, bvh_[0], bvh_[2]);
                    MMA_BF16(accO[2*ng+1], ph_, bvh_[1], bvh_[3]);
                    MMA_BF16(accO[2*ng],   ph_, bvl_[0], bvl_[2]);
                    MMA_BF16(accO[2*ng+1], ph_, bvl_[1], bvl_[3]);
                    MMA_BF16(accO[2*ng],   pl_, bvh_[0], bvh_[2]);
                    MMA_BF16(accO[2*ng+1], pl_, bvh_[1], bvh_[3]);
                }
            }
            __syncthreads();
        }

        const float inv0 = 1.0f / lrow0, inv1 = 1.0f / lrow1;
        __nv_bfloat16* o0h = oh + rowg0 * DD + h * DHH + 2 * t4;
        __nv_bfloat16* o0l = ol + rowg0 * DD + h * DHH + 2 * t4;
#pragma unroll
        for (int j = 0; j < 8; j++) {
            u32 hp, lp;
            split2(accO[j][0] * inv0, accO[j][1] * inv0, hp, lp);
            *(u32*)(o0h + 8 * j) = hp;
            *(u32*)(o0l + 8 * j) = lp;
            split2(accO[j][2] * inv1, accO[j][3] * inv1, hp, lp);
            *(u32*)(o0h + 8 * DD + 8 * j) = hp;
            *(u32*)(o0l + 8 * DD + 8 * j) = lp;
        }
    }
}

// ---------------------------------------------------------------------------
// Launch
// ---------------------------------------------------------------------------
extern "C" void kernel_launch(void* const* d_in, const int* in_sizes, int n_in,
                              void* d_out, int out_size)
{
    const float* x   = (const float*)d_in[0];
    // d_in[1] = mask — handled analytically
    const float* wq  = (const float*)d_in[2];
    const float* bq  = (const float*)d_in[3];
    const float* wk  = (const float*)d_in[4];
    const float* bk  = (const float*)d_in[5];
    const float* wv  = (const float*)d_in[6];
    const float* bv  = (const float*)d_in[7];
    const float* rel = (const float*)d_in[8];
    const float* w1  = (const float*)d_in[9];
    const float* b1  = (const float*)d_in[10];
    const float* w2  = (const float*)d_in[11];
    const float* b2  = (const float*)d_in[12];
    float* out = (float*)d_out;

    float* Vp;
    __nv_bfloat16 *xh, *xl, *qh, *ql, *kh, *kl, *vth, *vtl, *relh, *rell;
    __nv_bfloat16 *ah, *al, *hhp, *hlp;
    __nv_bfloat16 *wqh, *wql, *wkh, *wkl, *wvh, *wvl, *w1h, *w1l, *w2h, *w2l;
    cudaGetSymbolAddress((void**)&Vp,  g_V);
    cudaGetSymbolAddress((void**)&xh,  g_xh);   cudaGetSymbolAddress((void**)&xl,  g_xl);
    cudaGetSymbolAddress((void**)&qh,  g_qh);   cudaGetSymbolAddress((void**)&ql,  g_ql);
    cudaGetSymbolAddress((void**)&kh,  g_kh);   cudaGetSymbolAddress((void**)&kl,  g_kl);
    cudaGetSymbolAddress((void**)&vth, g_vth);  cudaGetSymbolAddress((void**)&vtl, g_vtl);
    cudaGetSymbolAddress((void**)&relh, g_relh); cudaGetSymbolAddress((void**)&rell, g_rell);
    cudaGetSymbolAddress((void**)&ah,  g_ah);   cudaGetSymbolAddress((void**)&al,  g_al);
    cudaGetSymbolAddress((void**)&hhp, g_hh);   cudaGetSymbolAddress((void**)&hlp, g_hl);
    cudaGetSymbolAddress((void**)&wqh, g_wqh);  cudaGetSymbolAddress((void**)&wql, g_wql);
    cudaGetSymbolAddress((void**)&wkh, g_wkh);  cudaGetSymbolAddress((void**)&wkl, g_wkl);
    cudaGetSymbolAddress((void**)&wvh, g_wvh);  cudaGetSymbolAddress((void**)&wvl, g_wvl);
    cudaGetSymbolAddress((void**)&w1h, g_w1h);  cudaGetSymbolAddress((void**)&w1l, g_w1l);
    cudaGetSymbolAddress((void**)&w2h, g_w2h);  cudaGetSymbolAddress((void**)&w2l, g_w2l);

    cudaFuncSetAttribute(tgemm_kernel<0>,  cudaFuncAttributeMaxDynamicSharedMemorySize, TGX_SMEM);
    cudaFuncSetAttribute(tgemm_kernel<1>,  cudaFuncAttributeMaxDynamicSharedMemorySize, TGX_SMEM);
    cudaFuncSetAttribute(qkv_fused_kernel, cudaFuncAttributeMaxDynamicSharedMemorySize, TGX_SMEM);
    cudaFuncSetAttribute(attn_mma_kernel,  cudaFuncAttributeMaxDynamicSharedMemorySize, AT_SMEM);

    // 0) Prep: split x+rel (1 launch), transpose wq/wk/wv (1 launch), w1, w2
    conv_xrel_kernel<<<(N4X + N4R + 255) / 256, 256>>>(
        (const float4*)x, (const float4*)rel, xh, xl, relh, rell);
    tsplit3_kernel<<<dim3(DD / 32, DD / 32, 3), 256>>>(
        wq, wk, wv, wqh, wql, wkh, wkl, wvh, wvl);
    transpose_split_kernel<<<dim3(DFCN / 32, DD / 32),   256>>>(w1, w1h, w1l, DD,   DFCN);
    transpose_split_kernel<<<dim3(DD / 32,   DFCN / 32), 256>>>(w2, w2h, w2l, DFCN, DD);

    // 1) Fused QKV (z selects matrix; Q scaled 1/8)
    qkv_fused_kernel<<<dim3(DD / 128, MM / 128, 3), 256, TGX_SMEM>>>(
        xh, xl, wqh, wql, wkh, wkl, wvh, wvl, bq, bk, bv, qh, ql, kh, kl, Vp);
    vt_split_kernel<<<dim3(DD / 32, MM / 32), 256>>>(Vp, vth, vtl);

    // 2) HMMA flash attention with relative bias
    attn_mma_kernel<<<128, 256, AT_SMEM>>>(qh, ql, kh, kl, vth, vtl, relh, rell, ah, al);

    // 3) FFN
    tgemm_kernel<1><<<dim3(DFCN / 128, MM / 128), 256, TGX_SMEM>>>(
        ah, al, w1h, w1l, b1, nullptr, hhp, hlp, MM, DFCN, DD, 1.0f);
    tgemm_kernel<0><<<dim3(DD / 128, MM / 128), 256, TGX_SMEM>>>(
        hhp, hlp, w2h, w2l, b2, out, nullptr, nullptr, MM, DD, DFCN, 1.0f);
}